// round 1
// baseline (speedup 1.0000x reference)
#include <cuda_runtime.h>
#include <math.h>

#define B 4
#define S 2048
#define H 768
#define NH 12
#define HD 64
#define E 8
#define TOPK 2
#define F 3072
#define T (B*S)      /* 8192 tokens */
#define H3 (3*H)     /* 2304 */

// ---------------- scratch (device globals: no runtime allocation) ----------
__device__ float g_qkv[(size_t)T*H3];        // 75.5 MB
__device__ float g_ctx[(size_t)T*H];         // 25 MB
__device__ float g_attn[(size_t)T*H];
__device__ float g_x1[(size_t)T*H];
__device__ float g_moe[(size_t)T*H];
__device__ float g_hmid[(size_t)E*T*F];      // 805 MB (worst-case all tokens one expert)
__device__ int   g_cnt[E];
__device__ float g_probsum[E];
__device__ int   g_tok[E*T];
__device__ float g_wgt[E*T];

// ---------------- zero scratch that must start at 0 each call --------------
__global__ void zero_kernel() {
    size_t n = (size_t)T * H;
    size_t stride = (size_t)gridDim.x * blockDim.x;
    for (size_t i = (size_t)blockIdx.x * blockDim.x + threadIdx.x; i < n; i += stride)
        g_moe[i] = 0.f;
    if (blockIdx.x == 0 && threadIdx.x < E) {
        g_cnt[threadIdx.x] = 0;
        g_probsum[threadIdx.x] = 0.f;
    }
}

// ---------------- generic fp32 SGEMM: C[M,N] = A[M,K] @ B[K,N] -------------
// 64x64 tile, BK=16, 256 threads, 4x4 micro-tile. All dims multiples of 64/16.
__global__ void __launch_bounds__(256) sgemm_kernel(
    const float* __restrict__ A, const float* __restrict__ Bm,
    float* __restrict__ C, int M, int N, int K)
{
    __shared__ float As[64][16];
    __shared__ float Bs[16][64];
    int tid = threadIdx.x;
    int tx = tid & 15, ty = tid >> 4;
    int row0 = blockIdx.y * 64, col0 = blockIdx.x * 64;
    float acc[4][4] = {};
    for (int k0 = 0; k0 < K; k0 += 16) {
#pragma unroll
        for (int i = 0; i < 4; i++) {
            int idx = tid + i * 256;
            int r = idx >> 4, c = idx & 15;
            As[r][c] = A[(size_t)(row0 + r) * K + k0 + c];
        }
#pragma unroll
        for (int i = 0; i < 4; i++) {
            int idx = tid + i * 256;
            int r = idx >> 6, c = idx & 63;
            Bs[r][c] = Bm[(size_t)(k0 + r) * N + col0 + c];
        }
        __syncthreads();
#pragma unroll
        for (int kk = 0; kk < 16; kk++) {
            float a[4], bb[4];
#pragma unroll
            for (int i = 0; i < 4; i++) a[i] = As[ty * 4 + i][kk];
            float4 bv = *(const float4*)&Bs[kk][tx * 4];
            bb[0] = bv.x; bb[1] = bv.y; bb[2] = bv.z; bb[3] = bv.w;
#pragma unroll
            for (int i = 0; i < 4; i++)
#pragma unroll
                for (int j = 0; j < 4; j++) acc[i][j] += a[i] * bb[j];
        }
        __syncthreads();
    }
#pragma unroll
    for (int i = 0; i < 4; i++) {
        float* cr = C + (size_t)(row0 + ty * 4 + i) * N + col0 + tx * 4;
        *(float4*)cr = make_float4(acc[i][0], acc[i][1], acc[i][2], acc[i][3]);
    }
}

// ---------------- RoPE applied in-place to q,k inside g_qkv ----------------
__global__ void rope_kernel() {
    int idx = blockIdx.x * blockDim.x + threadIdx.x;
    if (idx >= T * NH * 32) return;
    int i = idx & 31;
    int h = (idx >> 5) % NH;
    int t = idx / (32 * NH);
    int s = t % S;
    float invf = expf(-(float)i * (9.210340371976184f / 32.f)); // 10000^(-i/32)
    float th = (float)s * invf;
    float c = cosf(th), sn = sinf(th);
    float* p = g_qkv + (size_t)t * H3 + h * 192;
    float q1 = p[i], q2 = p[i + 32];
    p[i]      = q1 * c - q2 * sn;
    p[i + 32] = q2 * c + q1 * sn;
    float k1 = p[64 + i], k2 = p[64 + i + 32];
    p[64 + i]      = k1 * c - k2 * sn;
    p[64 + i + 32] = k2 * c + k1 * sn;
}

// ---------------- flash attention (fp32, online softmax) -------------------
// grid (S/128, NH, B), block 128: each thread owns one query row.
__global__ void __launch_bounds__(128) flash_kernel(const int* __restrict__ mask) {
    int tid = threadIdx.x;
    int q_s = blockIdx.x * 128 + tid;
    int h = blockIdx.y, b = blockIdx.z;
    const float* base = g_qkv + (size_t)b * S * H3 + (size_t)h * 192;
    const float* qp = base + (size_t)q_s * H3;
    float q[HD];
#pragma unroll
    for (int d = 0; d < HD; d += 4) {
        float4 v = *(const float4*)(qp + d);
        q[d] = v.x * 0.125f; q[d + 1] = v.y * 0.125f;
        q[d + 2] = v.z * 0.125f; q[d + 3] = v.w * 0.125f;
    }
    float acc[HD];
#pragma unroll
    for (int d = 0; d < HD; d++) acc[d] = 0.f;
    float m = -3.4028235e38f, l = 0.f;
    __shared__ float Ks[32][HD];
    __shared__ float Vs[32][HD];
    __shared__ float Ms[32];
    for (int k0 = 0; k0 < S; k0 += 32) {
        for (int i = tid; i < 32 * HD; i += 128) {
            int kk = i >> 6, d = i & 63;
            const float* kp = base + (size_t)(k0 + kk) * H3;
            Ks[kk][d] = kp[64 + d];
            Vs[kk][d] = kp[128 + d];
        }
        if (tid < 32) Ms[tid] = (mask[b * S + k0 + tid] == 0) ? -1.f : 0.f;
        __syncthreads();
        float sc[32];
        float tmax = m;
#pragma unroll 4
        for (int kk = 0; kk < 32; kk++) {
            float s = 0.f;
#pragma unroll
            for (int d = 0; d < HD; d++) s += q[d] * Ks[kk][d];
            s = (Ms[kk] < 0.f) ? -3.4028235e38f : s;
            sc[kk] = s;
            tmax = fmaxf(tmax, s);
        }
        float scale = expf(m - tmax);
        m = tmax;
        l *= scale;
#pragma unroll
        for (int d = 0; d < HD; d++) acc[d] *= scale;
#pragma unroll 4
        for (int kk = 0; kk < 32; kk++) {
            float p = expf(sc[kk] - m);
            l += p;
#pragma unroll
            for (int d = 0; d < HD; d++) acc[d] += p * Vs[kk][d];
        }
        __syncthreads();
    }
    float inv = 1.f / l;
    float* out = g_ctx + (size_t)(b * S + q_s) * H + h * HD;
#pragma unroll
    for (int d = 0; d < HD; d++) out[d] = acc[d] * inv;
}

// ---------------- residual add + RMSNorm -----------------------------------
__global__ void addnorm_kernel(const float* __restrict__ a, const float* __restrict__ bb,
                               const float* __restrict__ w, float* __restrict__ out) {
    __shared__ float buf[H];
    __shared__ float red[8];
    int t = blockIdx.x, tid = threadIdx.x;
    float ss = 0.f;
    for (int d = tid; d < H; d += 256) {
        float v = a[(size_t)t * H + d] + bb[(size_t)t * H + d];
        buf[d] = v;
        ss += v * v;
    }
    for (int o = 16; o; o >>= 1) ss += __shfl_xor_sync(~0u, ss, o);
    if ((tid & 31) == 0) red[tid >> 5] = ss;
    __syncthreads();
    if (tid < 8) {
        float x = red[tid];
        for (int o = 4; o; o >>= 1) x += __shfl_xor_sync(0xffu, x, o);
        if (tid == 0) red[0] = x;
    }
    __syncthreads();
    float inv = rsqrtf(red[0] / (float)H + 1.1920929e-7f);
    for (int d = tid; d < H; d += 256)
        out[(size_t)t * H + d] = buf[d] * inv * w[d];
}

// ---------------- router: logits, softmax, top-2, expert lists -------------
__global__ void router_kernel(const float* __restrict__ gate_w) {
    int warp = threadIdx.x >> 5, lane = threadIdx.x & 31;
    int t = blockIdx.x * 8 + warp;
    float acc[E];
#pragma unroll
    for (int e = 0; e < E; e++) acc[e] = 0.f;
    const float* xr = g_x1 + (size_t)t * H;
    for (int d = lane; d < H; d += 32) {
        float xv = xr[d];
        const float* g = gate_w + (size_t)d * E;
#pragma unroll
        for (int e = 0; e < E; e++) acc[e] += xv * g[e];
    }
#pragma unroll
    for (int e = 0; e < E; e++)
        for (int o = 16; o; o >>= 1) acc[e] += __shfl_xor_sync(~0u, acc[e], o);
    if (lane == 0) {
        float mx = acc[0];
#pragma unroll
        for (int e = 1; e < E; e++) mx = fmaxf(mx, acc[e]);
        float p[E]; float sum = 0.f;
#pragma unroll
        for (int e = 0; e < E; e++) { p[e] = expf(acc[e] - mx); sum += p[e]; }
        float inv = 1.f / sum;
#pragma unroll
        for (int e = 0; e < E; e++) p[e] *= inv;
        int i1 = 0;
#pragma unroll
        for (int e = 1; e < E; e++) if (p[e] > p[i1]) i1 = e;
        int i2 = -1;
#pragma unroll
        for (int e = 0; e < E; e++) {
            if (e == i1) continue;
            if (i2 < 0 || p[e] > p[i2]) i2 = e;
        }
        float s2 = p[i1] + p[i2];
        float w1n = p[i1] / s2, w2n = p[i2] / s2;
        int pos = atomicAdd(&g_cnt[i1], 1);
        g_tok[i1 * T + pos] = t; g_wgt[i1 * T + pos] = w1n;
        pos = atomicAdd(&g_cnt[i2], 1);
        g_tok[i2 * T + pos] = t; g_wgt[i2 * T + pos] = w2n;
#pragma unroll
        for (int e = 0; e < E; e++) atomicAdd(&g_probsum[e], p[e]);
    }
}

__global__ void aux_kernel(float* out) {
    float a = 0.f;
    for (int e = 0; e < E; e++)
        a += ((float)g_cnt[e] / (float)T) * (g_probsum[e] / (float)T);
    out[0] = (float)E * a;
}

// ---------------- MoE GEMM1: gathered x1 @ w1[e], GELU epilogue ------------
// grid (F/64, T/64, E)
__global__ void __launch_bounds__(256) moe_gemm1(const float* __restrict__ w1) {
    int e = blockIdx.z;
    int c = g_cnt[e];
    int r0 = blockIdx.y * 64;
    if (r0 >= c) return;
    int n0 = blockIdx.x * 64;
    __shared__ float As[64][16];
    __shared__ float Bs[16][64];
    __shared__ int rt[64];
    int tid = threadIdx.x, tx = tid & 15, ty = tid >> 4;
    if (tid < 64) {
        int r = r0 + tid;
        rt[tid] = (r < c) ? g_tok[e * T + r] : -1;
    }
    __syncthreads();
    const float* Wb = w1 + (size_t)e * H * F;
    float acc[4][4] = {};
    for (int k0 = 0; k0 < H; k0 += 16) {
#pragma unroll
        for (int i = 0; i < 4; i++) {
            int idx = tid + i * 256, r = idx >> 4, cc = idx & 15;
            int tt = rt[r];
            As[r][cc] = (tt >= 0) ? g_x1[(size_t)tt * H + k0 + cc] : 0.f;
        }
#pragma unroll
        for (int i = 0; i < 4; i++) {
            int idx = tid + i * 256, r = idx >> 6, cc = idx & 63;
            Bs[r][cc] = Wb[(size_t)(k0 + r) * F + n0 + cc];
        }
        __syncthreads();
#pragma unroll
        for (int kk = 0; kk < 16; kk++) {
            float a[4], bb[4];
#pragma unroll
            for (int i = 0; i < 4; i++) a[i] = As[ty * 4 + i][kk];
            float4 bv = *(const float4*)&Bs[kk][tx * 4];
            bb[0] = bv.x; bb[1] = bv.y; bb[2] = bv.z; bb[3] = bv.w;
#pragma unroll
            for (int i = 0; i < 4; i++)
#pragma unroll
                for (int j = 0; j < 4; j++) acc[i][j] += a[i] * bb[j];
        }
        __syncthreads();
    }
#pragma unroll
    for (int i = 0; i < 4; i++) {
        int r = r0 + ty * 4 + i;
        if (r >= c) continue;
#pragma unroll
        for (int j = 0; j < 4; j++) {
            float x = acc[i][j];
            float gel = 0.5f * x * (1.f + erff(x * 0.70710678118f));
            g_hmid[((size_t)e * T + r) * F + n0 + tx * 4 + j] = gel;
        }
    }
}

// ---------------- MoE GEMM2: hmid @ w2[e], weighted atomic scatter ---------
// grid (H/64, T/64, E)
__global__ void __launch_bounds__(256) moe_gemm2(const float* __restrict__ w2) {
    int e = blockIdx.z;
    int c = g_cnt[e];
    int r0 = blockIdx.y * 64;
    if (r0 >= c) return;
    int n0 = blockIdx.x * 64;
    __shared__ float As[64][16];
    __shared__ float Bs[16][64];
    __shared__ int rt[64];
    __shared__ float rw[64];
    int tid = threadIdx.x, tx = tid & 15, ty = tid >> 4;
    if (tid < 64) {
        int r = r0 + tid;
        rt[tid] = (r < c) ? g_tok[e * T + r] : -1;
        rw[tid] = (r < c) ? g_wgt[e * T + r] : 0.f;
    }
    __syncthreads();
    const float* Wb = w2 + (size_t)e * F * H;
    float acc[4][4] = {};
    for (int k0 = 0; k0 < F; k0 += 16) {
#pragma unroll
        for (int i = 0; i < 4; i++) {
            int idx = tid + i * 256, r = idx >> 4, cc = idx & 15;
            As[r][cc] = (r0 + r < c) ? g_hmid[((size_t)e * T + r0 + r) * F + k0 + cc] : 0.f;
        }
#pragma unroll
        for (int i = 0; i < 4; i++) {
            int idx = tid + i * 256, r = idx >> 6, cc = idx & 63;
            Bs[r][cc] = Wb[(size_t)(k0 + r) * H + n0 + cc];
        }
        __syncthreads();
#pragma unroll
        for (int kk = 0; kk < 16; kk++) {
            float a[4], bb[4];
#pragma unroll
            for (int i = 0; i < 4; i++) a[i] = As[ty * 4 + i][kk];
            float4 bv = *(const float4*)&Bs[kk][tx * 4];
            bb[0] = bv.x; bb[1] = bv.y; bb[2] = bv.z; bb[3] = bv.w;
#pragma unroll
            for (int i = 0; i < 4; i++)
#pragma unroll
                for (int j = 0; j < 4; j++) acc[i][j] += a[i] * bb[j];
        }
        __syncthreads();
    }
#pragma unroll
    for (int i = 0; i < 4; i++) {
        int li = ty * 4 + i;
        int tt = rt[li];
        if (tt < 0) continue;
        float w = rw[li];
#pragma unroll
        for (int j = 0; j < 4; j++)
            atomicAdd(&g_moe[(size_t)tt * H + n0 + tx * 4 + j], acc[i][j] * w);
    }
}

// ---------------------------------------------------------------------------
extern "C" void kernel_launch(void* const* d_in, const int* in_sizes, int n_in,
                              void* d_out, int out_size) {
    const float* x      = (const float*)d_in[0];
    const int*   mask   = (const int*)  d_in[1];
    const float* qkv_w  = (const float*)d_in[2];
    const float* out_w  = (const float*)d_in[3];
    const float* gate_w = (const float*)d_in[4];
    const float* w1     = (const float*)d_in[5];
    const float* w2     = (const float*)d_in[6];
    const float* n1     = (const float*)d_in[7];
    const float* n2     = (const float*)d_in[8];
    float* out = (float*)d_out;

    float *p_qkv, *p_ctx, *p_attn, *p_x1, *p_moe;
    cudaGetSymbolAddress((void**)&p_qkv,  g_qkv);
    cudaGetSymbolAddress((void**)&p_ctx,  g_ctx);
    cudaGetSymbolAddress((void**)&p_attn, g_attn);
    cudaGetSymbolAddress((void**)&p_x1,   g_x1);
    cudaGetSymbolAddress((void**)&p_moe,  g_moe);

    zero_kernel<<<1024, 256>>>();

    // QKV projection: [T,H] @ [H,3H]
    sgemm_kernel<<<dim3(H3 / 64, T / 64), 256>>>(x, qkv_w, p_qkv, T, H3, H);

    // RoPE in-place on q,k
    rope_kernel<<<(T * NH * 32 + 255) / 256, 256>>>();

    // attention -> ctx
    flash_kernel<<<dim3(S / 128, NH, B), 128>>>(mask);

    // out projection
    sgemm_kernel<<<dim3(H / 64, T / 64), 256>>>(p_ctx, out_w, p_attn, T, H, H);

    // x1 = rmsnorm(x + attn_out)
    addnorm_kernel<<<T, 256>>>(x, p_attn, n1, p_x1);

    // router + expert lists
    router_kernel<<<T / 8, 256>>>(gate_w);
    aux_kernel<<<1, 1>>>(out + (size_t)T * H);

    // MoE (only selected experts' tokens)
    moe_gemm1<<<dim3(F / 64, T / 64, E), 256>>>(w1);
    moe_gemm2<<<dim3(H / 64, T / 64, E), 256>>>(w2);

    // x2 = rmsnorm(x1 + moe_out)
    addnorm_kernel<<<T, 256>>>(p_x1, p_moe, n2, out);
}

// round 2
// speedup vs baseline: 1.0006x; 1.0006x over previous
#include <cuda_runtime.h>
#include <math.h>

#define B 4
#define S 2048
#define H 768
#define NH 12
#define HD 64
#define E 8
#define TOPK 2
#define F 3072
#define T (B*S)      /* 8192 tokens */
#define H3 (3*H)     /* 2304 */

// ---------------- scratch (device globals: no runtime allocation) ----------
__device__ float g_qkv[(size_t)T*H3];        // 75.5 MB
__device__ float g_ctx[(size_t)T*H];         // 25 MB
__device__ float g_attn[(size_t)T*H];
__device__ float g_x1[(size_t)T*H];
__device__ float g_moe[(size_t)T*H];
__device__ float g_hmid[(size_t)E*T*F];      // 805 MB (worst-case all tokens one expert)
__device__ int   g_cnt[E];
__device__ float g_probsum[E];
__device__ int   g_tok[E*T];
__device__ float g_wgt[E*T];

// ---------------- zero scratch that must start at 0 each call --------------
__global__ void zero_kernel() {
    size_t n = (size_t)T * H;
    size_t stride = (size_t)gridDim.x * blockDim.x;
    for (size_t i = (size_t)blockIdx.x * blockDim.x + threadIdx.x; i < n; i += stride)
        g_moe[i] = 0.f;
    if (blockIdx.x == 0 && threadIdx.x < E) {
        g_cnt[threadIdx.x] = 0;
        g_probsum[threadIdx.x] = 0.f;
    }
}

// ---------------- generic fp32 SGEMM: C[M,N] = A[M,K] @ B[K,N] -------------
// 64x64 tile, BK=16, 256 threads, 4x4 micro-tile. All dims multiples of 64/16.
__global__ void __launch_bounds__(256) sgemm_kernel(
    const float* __restrict__ A, const float* __restrict__ Bm,
    float* __restrict__ C, int M, int N, int K)
{
    __shared__ float As[64][16];
    __shared__ float Bs[16][64];
    int tid = threadIdx.x;
    int tx = tid & 15, ty = tid >> 4;
    int row0 = blockIdx.y * 64, col0 = blockIdx.x * 64;
    float acc[4][4] = {};
    for (int k0 = 0; k0 < K; k0 += 16) {
#pragma unroll
        for (int i = 0; i < 4; i++) {
            int idx = tid + i * 256;
            int r = idx >> 4, c = idx & 15;
            As[r][c] = A[(size_t)(row0 + r) * K + k0 + c];
        }
#pragma unroll
        for (int i = 0; i < 4; i++) {
            int idx = tid + i * 256;
            int r = idx >> 6, c = idx & 63;
            Bs[r][c] = Bm[(size_t)(k0 + r) * N + col0 + c];
        }
        __syncthreads();
#pragma unroll
        for (int kk = 0; kk < 16; kk++) {
            float a[4], bb[4];
#pragma unroll
            for (int i = 0; i < 4; i++) a[i] = As[ty * 4 + i][kk];
            float4 bv = *(const float4*)&Bs[kk][tx * 4];
            bb[0] = bv.x; bb[1] = bv.y; bb[2] = bv.z; bb[3] = bv.w;
#pragma unroll
            for (int i = 0; i < 4; i++)
#pragma unroll
                for (int j = 0; j < 4; j++) acc[i][j] += a[i] * bb[j];
        }
        __syncthreads();
    }
#pragma unroll
    for (int i = 0; i < 4; i++) {
        float* cr = C + (size_t)(row0 + ty * 4 + i) * N + col0 + tx * 4;
        *(float4*)cr = make_float4(acc[i][0], acc[i][1], acc[i][2], acc[i][3]);
    }
}

// ---------------- RoPE applied in-place to q,k inside g_qkv ----------------
__global__ void rope_kernel() {
    int idx = blockIdx.x * blockDim.x + threadIdx.x;
    if (idx >= T * NH * 32) return;
    int i = idx & 31;
    int h = (idx >> 5) % NH;
    int t = idx / (32 * NH);
    int s = t % S;
    float invf = expf(-(float)i * (9.210340371976184f / 32.f)); // 10000^(-i/32)
    float th = (float)s * invf;
    float c = cosf(th), sn = sinf(th);
    float* p = g_qkv + (size_t)t * H3 + h * 192;
    float q1 = p[i], q2 = p[i + 32];
    p[i]      = q1 * c - q2 * sn;
    p[i + 32] = q2 * c + q1 * sn;
    float k1 = p[64 + i], k2 = p[64 + i + 32];
    p[64 + i]      = k1 * c - k2 * sn;
    p[64 + i + 32] = k2 * c + k1 * sn;
}

// ---------------- flash attention (fp32, online softmax) -------------------
// grid (S/128, NH, B), block 128: each thread owns one query row.
__global__ void __launch_bounds__(128) flash_kernel(const int* __restrict__ mask) {
    int tid = threadIdx.x;
    int q_s = blockIdx.x * 128 + tid;
    int h = blockIdx.y, b = blockIdx.z;
    const float* base = g_qkv + (size_t)b * S * H3 + (size_t)h * 192;
    const float* qp = base + (size_t)q_s * H3;
    float q[HD];
#pragma unroll
    for (int d = 0; d < HD; d += 4) {
        float4 v = *(const float4*)(qp + d);
        q[d] = v.x * 0.125f; q[d + 1] = v.y * 0.125f;
        q[d + 2] = v.z * 0.125f; q[d + 3] = v.w * 0.125f;
    }
    float acc[HD];
#pragma unroll
    for (int d = 0; d < HD; d++) acc[d] = 0.f;
    float m = -3.4028235e38f, l = 0.f;
    __shared__ float Ks[32][HD];
    __shared__ float Vs[32][HD];
    __shared__ float Ms[32];
    for (int k0 = 0; k0 < S; k0 += 32) {
        for (int i = tid; i < 32 * HD; i += 128) {
            int kk = i >> 6, d = i & 63;
            const float* kp = base + (size_t)(k0 + kk) * H3;
            Ks[kk][d] = kp[64 + d];
            Vs[kk][d] = kp[128 + d];
        }
        if (tid < 32) Ms[tid] = (mask[b * S + k0 + tid] == 0) ? -1.f : 0.f;
        __syncthreads();
        float sc[32];
        float tmax = m;
#pragma unroll 4
        for (int kk = 0; kk < 32; kk++) {
            float s = 0.f;
#pragma unroll
            for (int d = 0; d < HD; d++) s += q[d] * Ks[kk][d];
            s = (Ms[kk] < 0.f) ? -3.4028235e38f : s;
            sc[kk] = s;
            tmax = fmaxf(tmax, s);
        }
        float scale = expf(m - tmax);
        m = tmax;
        l *= scale;
#pragma unroll
        for (int d = 0; d < HD; d++) acc[d] *= scale;
#pragma unroll 4
        for (int kk = 0; kk < 32; kk++) {
            float p = expf(sc[kk] - m);
            l += p;
#pragma unroll
            for (int d = 0; d < HD; d++) acc[d] += p * Vs[kk][d];
        }
        __syncthreads();
    }
    float inv = 1.f / l;
    float* out = g_ctx + (size_t)(b * S + q_s) * H + h * HD;
#pragma unroll
    for (int d = 0; d < HD; d++) out[d] = acc[d] * inv;
}

// ---------------- residual add + RMSNorm -----------------------------------
__global__ void addnorm_kernel(const float* __restrict__ a, const float* __restrict__ bb,
                               const float* __restrict__ w, float* __restrict__ out) {
    __shared__ float buf[H];
    __shared__ float red[8];
    int t = blockIdx.x, tid = threadIdx.x;
    float ss = 0.f;
    for (int d = tid; d < H; d += 256) {
        float v = a[(size_t)t * H + d] + bb[(size_t)t * H + d];
        buf[d] = v;
        ss += v * v;
    }
    for (int o = 16; o; o >>= 1) ss += __shfl_xor_sync(~0u, ss, o);
    if ((tid & 31) == 0) red[tid >> 5] = ss;
    __syncthreads();
    if (tid < 8) {
        float x = red[tid];
        for (int o = 4; o; o >>= 1) x += __shfl_xor_sync(0xffu, x, o);
        if (tid == 0) red[0] = x;
    }
    __syncthreads();
    float inv = rsqrtf(red[0] / (float)H + 1.1920929e-7f);
    for (int d = tid; d < H; d += 256)
        out[(size_t)t * H + d] = buf[d] * inv * w[d];
}

// ---------------- router: logits, softmax, top-2, expert lists -------------
__global__ void router_kernel(const float* __restrict__ gate_w) {
    int warp = threadIdx.x >> 5, lane = threadIdx.x & 31;
    int t = blockIdx.x * 8 + warp;
    float acc[E];
#pragma unroll
    for (int e = 0; e < E; e++) acc[e] = 0.f;
    const float* xr = g_x1 + (size_t)t * H;
    for (int d = lane; d < H; d += 32) {
        float xv = xr[d];
        const float* g = gate_w + (size_t)d * E;
#pragma unroll
        for (int e = 0; e < E; e++) acc[e] += xv * g[e];
    }
#pragma unroll
    for (int e = 0; e < E; e++)
        for (int o = 16; o; o >>= 1) acc[e] += __shfl_xor_sync(~0u, acc[e], o);
    if (lane == 0) {
        float mx = acc[0];
#pragma unroll
        for (int e = 1; e < E; e++) mx = fmaxf(mx, acc[e]);
        float p[E]; float sum = 0.f;
#pragma unroll
        for (int e = 0; e < E; e++) { p[e] = expf(acc[e] - mx); sum += p[e]; }
        float inv = 1.f / sum;
#pragma unroll
        for (int e = 0; e < E; e++) p[e] *= inv;
        int i1 = 0;
#pragma unroll
        for (int e = 1; e < E; e++) if (p[e] > p[i1]) i1 = e;
        int i2 = -1;
#pragma unroll
        for (int e = 0; e < E; e++) {
            if (e == i1) continue;
            if (i2 < 0 || p[e] > p[i2]) i2 = e;
        }
        float s2 = p[i1] + p[i2];
        float w1n = p[i1] / s2, w2n = p[i2] / s2;
        int pos = atomicAdd(&g_cnt[i1], 1);
        g_tok[i1 * T + pos] = t; g_wgt[i1 * T + pos] = w1n;
        pos = atomicAdd(&g_cnt[i2], 1);
        g_tok[i2 * T + pos] = t; g_wgt[i2 * T + pos] = w2n;
#pragma unroll
        for (int e = 0; e < E; e++) atomicAdd(&g_probsum[e], p[e]);
    }
}

__global__ void aux_kernel(float* out) {
    float a = 0.f;
    for (int e = 0; e < E; e++)
        a += ((float)g_cnt[e] / (float)T) * (g_probsum[e] / (float)T);
    out[0] = (float)E * a;
}

// ---------------- MoE GEMM1: gathered x1 @ w1[e], GELU epilogue ------------
// grid (F/64, T/64, E)
__global__ void __launch_bounds__(256) moe_gemm1(const float* __restrict__ w1) {
    int e = blockIdx.z;
    int c = g_cnt[e];
    int r0 = blockIdx.y * 64;
    if (r0 >= c) return;
    int n0 = blockIdx.x * 64;
    __shared__ float As[64][16];
    __shared__ float Bs[16][64];
    __shared__ int rt[64];
    int tid = threadIdx.x, tx = tid & 15, ty = tid >> 4;
    if (tid < 64) {
        int r = r0 + tid;
        rt[tid] = (r < c) ? g_tok[e * T + r] : -1;
    }
    __syncthreads();
    const float* Wb = w1 + (size_t)e * H * F;
    float acc[4][4] = {};
    for (int k0 = 0; k0 < H; k0 += 16) {
#pragma unroll
        for (int i = 0; i < 4; i++) {
            int idx = tid + i * 256, r = idx >> 4, cc = idx & 15;
            int tt = rt[r];
            As[r][cc] = (tt >= 0) ? g_x1[(size_t)tt * H + k0 + cc] : 0.f;
        }
#pragma unroll
        for (int i = 0; i < 4; i++) {
            int idx = tid + i * 256, r = idx >> 6, cc = idx & 63;
            Bs[r][cc] = Wb[(size_t)(k0 + r) * F + n0 + cc];
        }
        __syncthreads();
#pragma unroll
        for (int kk = 0; kk < 16; kk++) {
            float a[4], bb[4];
#pragma unroll
            for (int i = 0; i < 4; i++) a[i] = As[ty * 4 + i][kk];
            float4 bv = *(const float4*)&Bs[kk][tx * 4];
            bb[0] = bv.x; bb[1] = bv.y; bb[2] = bv.z; bb[3] = bv.w;
#pragma unroll
            for (int i = 0; i < 4; i++)
#pragma unroll
                for (int j = 0; j < 4; j++) acc[i][j] += a[i] * bb[j];
        }
        __syncthreads();
    }
#pragma unroll
    for (int i = 0; i < 4; i++) {
        int r = r0 + ty * 4 + i;
        if (r >= c) continue;
#pragma unroll
        for (int j = 0; j < 4; j++) {
            float x = acc[i][j];
            float gel = 0.5f * x * (1.f + erff(x * 0.70710678118f));
            g_hmid[((size_t)e * T + r) * F + n0 + tx * 4 + j] = gel;
        }
    }
}

// ---------------- MoE GEMM2: hmid @ w2[e], weighted atomic scatter ---------
// grid (H/64, T/64, E)
__global__ void __launch_bounds__(256) moe_gemm2(const float* __restrict__ w2) {
    int e = blockIdx.z;
    int c = g_cnt[e];
    int r0 = blockIdx.y * 64;
    if (r0 >= c) return;
    int n0 = blockIdx.x * 64;
    __shared__ float As[64][16];
    __shared__ float Bs[16][64];
    __shared__ int rt[64];
    __shared__ float rw[64];
    int tid = threadIdx.x, tx = tid & 15, ty = tid >> 4;
    if (tid < 64) {
        int r = r0 + tid;
        rt[tid] = (r < c) ? g_tok[e * T + r] : -1;
        rw[tid] = (r < c) ? g_wgt[e * T + r] : 0.f;
    }
    __syncthreads();
    const float* Wb = w2 + (size_t)e * F * H;
    float acc[4][4] = {};
    for (int k0 = 0; k0 < F; k0 += 16) {
#pragma unroll
        for (int i = 0; i < 4; i++) {
            int idx = tid + i * 256, r = idx >> 4, cc = idx & 15;
            As[r][cc] = (r0 + r < c) ? g_hmid[((size_t)e * T + r0 + r) * F + k0 + cc] : 0.f;
        }
#pragma unroll
        for (int i = 0; i < 4; i++) {
            int idx = tid + i * 256, r = idx >> 6, cc = idx & 63;
            Bs[r][cc] = Wb[(size_t)(k0 + r) * H + n0 + cc];
        }
        __syncthreads();
#pragma unroll
        for (int kk = 0; kk < 16; kk++) {
            float a[4], bb[4];
#pragma unroll
            for (int i = 0; i < 4; i++) a[i] = As[ty * 4 + i][kk];
            float4 bv = *(const float4*)&Bs[kk][tx * 4];
            bb[0] = bv.x; bb[1] = bv.y; bb[2] = bv.z; bb[3] = bv.w;
#pragma unroll
            for (int i = 0; i < 4; i++)
#pragma unroll
                for (int j = 0; j < 4; j++) acc[i][j] += a[i] * bb[j];
        }
        __syncthreads();
    }
#pragma unroll
    for (int i = 0; i < 4; i++) {
        int li = ty * 4 + i;
        int tt = rt[li];
        if (tt < 0) continue;
        float w = rw[li];
#pragma unroll
        for (int j = 0; j < 4; j++)
            atomicAdd(&g_moe[(size_t)tt * H + n0 + tx * 4 + j], acc[i][j] * w);
    }
}

// ---------------------------------------------------------------------------
extern "C" void kernel_launch(void* const* d_in, const int* in_sizes, int n_in,
                              void* d_out, int out_size) {
    const float* x      = (const float*)d_in[0];
    const int*   mask   = (const int*)  d_in[1];
    const float* qkv_w  = (const float*)d_in[2];
    const float* out_w  = (const float*)d_in[3];
    const float* gate_w = (const float*)d_in[4];
    const float* w1     = (const float*)d_in[5];
    const float* w2     = (const float*)d_in[6];
    const float* n1     = (const float*)d_in[7];
    const float* n2     = (const float*)d_in[8];
    float* out = (float*)d_out;

    float *p_qkv, *p_ctx, *p_attn, *p_x1, *p_moe;
    cudaGetSymbolAddress((void**)&p_qkv,  g_qkv);
    cudaGetSymbolAddress((void**)&p_ctx,  g_ctx);
    cudaGetSymbolAddress((void**)&p_attn, g_attn);
    cudaGetSymbolAddress((void**)&p_x1,   g_x1);
    cudaGetSymbolAddress((void**)&p_moe,  g_moe);

    zero_kernel<<<1024, 256>>>();

    // QKV projection: [T,H] @ [H,3H]
    sgemm_kernel<<<dim3(H3 / 64, T / 64), 256>>>(x, qkv_w, p_qkv, T, H3, H);

    // RoPE in-place on q,k
    rope_kernel<<<(T * NH * 32 + 255) / 256, 256>>>();

    // attention -> ctx
    flash_kernel<<<dim3(S / 128, NH, B), 128>>>(mask);

    // out projection
    sgemm_kernel<<<dim3(H / 64, T / 64), 256>>>(p_ctx, out_w, p_attn, T, H, H);

    // x1 = rmsnorm(x + attn_out)
    addnorm_kernel<<<T, 256>>>(x, p_attn, n1, p_x1);

    // router + expert lists
    router_kernel<<<T / 8, 256>>>(gate_w);
    aux_kernel<<<1, 1>>>(out + (size_t)T * H);

    // MoE (only selected experts' tokens)
    moe_gemm1<<<dim3(F / 64, T / 64, E), 256>>>(w1);
    moe_gemm2<<<dim3(H / 64, T / 64, E), 256>>>(w2);

    // x2 = rmsnorm(x1 + moe_out)
    addnorm_kernel<<<T, 256>>>(p_x1, p_moe, n2, out);
}

// round 3
// speedup vs baseline: 1.7553x; 1.7542x over previous
#include <cuda_runtime.h>
#include <math.h>

#define B 4
#define S 2048
#define H 768
#define NH 12
#define HD 64
#define E 8
#define TOPK 2
#define F 3072
#define T (B*S)      /* 8192 tokens */
#define H3 (3*H)     /* 2304 */

// ---------------- scratch (device globals: no runtime allocation) ----------
__device__ float g_qkv[(size_t)T*H3];
__device__ float g_ctx[(size_t)T*H];
__device__ float g_attn[(size_t)T*H];
__device__ float g_x1[(size_t)T*H];
__device__ float g_hmid[(size_t)E*T*F];     // expert-local GELU activations
__device__ float g_ybuf[(size_t)E*T*H];     // expert-local GEMM2 outputs
__device__ int   g_cnt[E];
__device__ float g_probsum[E];
__device__ int   g_tok[E*T];
__device__ int   g_slot[T*TOPK];
__device__ float g_slotw[T*TOPK];

__global__ void zero_small() {
    if (threadIdx.x < E) { g_cnt[threadIdx.x] = 0; g_probsum[threadIdx.x] = 0.f; }
}

// ---------------- tf32 tensor-core GEMM ------------------------------------
// C[M,N] = A[M,K] @ W[K,N], 128x128x16 tiles, 256 threads, warp = 64x32.
// MODE 0: plain.  MODE 1: gather A rows via g_tok, GELU, write g_hmid.
// MODE 2: A = g_hmid (expert-local), write g_ybuf (expert-local).
#define BM 128
#define BN 128
#define BK 16

__device__ __forceinline__ unsigned f2tf(float x) {
    unsigned u; asm("cvt.rna.tf32.f32 %0, %1;" : "=r"(u) : "f"(x)); return u;
}

template<int MODE>
__global__ void __launch_bounds__(256) gemm_tf32(
    const float* __restrict__ A, const float* __restrict__ W,
    float* __restrict__ Cout, int M, int N, int K)
{
    __shared__ unsigned As[BK][BM + 4];
    __shared__ unsigned Bs[BK][BN + 4];
    __shared__ int rt_s[BM];

    int e = blockIdx.z;
    int c = M;
    int r0 = blockIdx.y * BM;
    if (MODE != 0) {
        c = g_cnt[e];
        if (r0 >= c) return;
    }
    int col0 = blockIdx.x * BN;
    int tid = threadIdx.x;

    const float* Ab = A;
    const float* Wb = W;
    if (MODE == 1) { Wb = W + (size_t)e * K * N; }
    if (MODE == 2) { Ab = A + (size_t)e * T * K; Wb = W + (size_t)e * K * N; }

    if (MODE == 1) {
        if (tid < BM) {
            int r = r0 + tid;
            rt_s[tid] = (r < c) ? g_tok[e * T + r] : -1;
        }
        __syncthreads();
    }

    int lane = tid & 31, warp = tid >> 5;
    int wm = warp >> 2, wn = warp & 3;
    int g = lane >> 2, cq = lane & 3;

    float acc[4][4][4];
#pragma unroll
    for (int i = 0; i < 4; i++)
#pragma unroll
        for (int j = 0; j < 4; j++)
#pragma unroll
            for (int k = 0; k < 4; k++) acc[i][j][k] = 0.f;

    for (int k0 = 0; k0 < K; k0 += BK) {
        // ---- stage A tile (128x16) ----
#pragma unroll
        for (int i = 0; i < 2; i++) {
            int lin = tid + i * 256;
            int r = lin >> 2, kq = (lin & 3) * 4;
            float4 v;
            if (MODE == 0) {
                v = *(const float4*)(Ab + (size_t)(r0 + r) * K + k0 + kq);
            } else if (MODE == 1) {
                int tt = rt_s[r];
                v = (tt >= 0) ? *(const float4*)(Ab + (size_t)tt * K + k0 + kq)
                              : make_float4(0.f, 0.f, 0.f, 0.f);
            } else {
                v = (r0 + r < c) ? *(const float4*)(Ab + (size_t)(r0 + r) * K + k0 + kq)
                                 : make_float4(0.f, 0.f, 0.f, 0.f);
            }
            As[kq + 0][r] = f2tf(v.x);
            As[kq + 1][r] = f2tf(v.y);
            As[kq + 2][r] = f2tf(v.z);
            As[kq + 3][r] = f2tf(v.w);
        }
        // ---- stage B tile (16x128) ----
#pragma unroll
        for (int i = 0; i < 2; i++) {
            int lin = tid + i * 256;
            int r = lin >> 5, nq = (lin & 31) * 4;
            float4 v = *(const float4*)(Wb + (size_t)(k0 + r) * N + col0 + nq);
            Bs[r][nq + 0] = f2tf(v.x);
            Bs[r][nq + 1] = f2tf(v.y);
            Bs[r][nq + 2] = f2tf(v.z);
            Bs[r][nq + 3] = f2tf(v.w);
        }
        __syncthreads();
#pragma unroll
        for (int kk = 0; kk < BK; kk += 8) {
            unsigned a[4][4], b[4][2];
#pragma unroll
            for (int mt = 0; mt < 4; mt++) {
                int m0 = wm * 64 + mt * 16;
                a[mt][0] = As[kk + cq    ][m0 + g    ];
                a[mt][1] = As[kk + cq    ][m0 + g + 8];
                a[mt][2] = As[kk + cq + 4][m0 + g    ];
                a[mt][3] = As[kk + cq + 4][m0 + g + 8];
            }
#pragma unroll
            for (int nt = 0; nt < 4; nt++) {
                int n0 = wn * 32 + nt * 8;
                b[nt][0] = Bs[kk + cq    ][n0 + g];
                b[nt][1] = Bs[kk + cq + 4][n0 + g];
            }
#pragma unroll
            for (int mt = 0; mt < 4; mt++)
#pragma unroll
                for (int nt = 0; nt < 4; nt++) {
                    asm volatile(
                        "mma.sync.aligned.m16n8k8.row.col.f32.tf32.tf32.f32 "
                        "{%0,%1,%2,%3},{%4,%5,%6,%7},{%8,%9},{%0,%1,%2,%3};"
                        : "+f"(acc[mt][nt][0]), "+f"(acc[mt][nt][1]),
                          "+f"(acc[mt][nt][2]), "+f"(acc[mt][nt][3])
                        : "r"(a[mt][0]), "r"(a[mt][1]), "r"(a[mt][2]), "r"(a[mt][3]),
                          "r"(b[nt][0]), "r"(b[nt][1]));
                }
        }
        __syncthreads();
    }

    // ---- epilogue ----
#pragma unroll
    for (int mt = 0; mt < 4; mt++) {
#pragma unroll
        for (int nt = 0; nt < 4; nt++) {
#pragma unroll
            for (int half = 0; half < 2; half++) {
                int lrow = wm * 64 + mt * 16 + g + half * 8;
                int col = col0 + wn * 32 + nt * 8 + cq * 2;
                float v0 = acc[mt][nt][half * 2 + 0];
                float v1 = acc[mt][nt][half * 2 + 1];
                if (MODE == 0) {
                    Cout[(size_t)(r0 + lrow) * N + col]     = v0;
                    Cout[(size_t)(r0 + lrow) * N + col + 1] = v1;
                } else if (MODE == 1) {
                    int r = r0 + lrow;
                    if (r < c) {
                        float g0 = 0.5f * v0 * (1.f + erff(v0 * 0.70710678118f));
                        float g1 = 0.5f * v1 * (1.f + erff(v1 * 0.70710678118f));
                        g_hmid[((size_t)e * T + r) * F + col]     = g0;
                        g_hmid[((size_t)e * T + r) * F + col + 1] = g1;
                    }
                } else {
                    int r = r0 + lrow;
                    if (r < c) {
                        g_ybuf[((size_t)e * T + r) * H + col]     = v0;
                        g_ybuf[((size_t)e * T + r) * H + col + 1] = v1;
                    }
                }
            }
        }
    }
}

// ---------------- RoPE applied in-place to q,k inside g_qkv ----------------
__global__ void rope_kernel() {
    int idx = blockIdx.x * blockDim.x + threadIdx.x;
    if (idx >= T * NH * 32) return;
    int i = idx & 31;
    int h = (idx >> 5) % NH;
    int t = idx / (32 * NH);
    int s = t % S;
    float invf = expf(-(float)i * (9.210340371976184f / 32.f));
    float th = (float)s * invf;
    float c = cosf(th), sn = sinf(th);
    float* p = g_qkv + (size_t)t * H3 + h * 192;
    float q1 = p[i], q2 = p[i + 32];
    p[i]      = q1 * c - q2 * sn;
    p[i + 32] = q2 * c + q1 * sn;
    float k1 = p[64 + i], k2 = p[64 + i + 32];
    p[64 + i]      = k1 * c - k2 * sn;
    p[64 + i + 32] = k2 * c + k1 * sn;
}

// ---------------- flash attention (fp32, online softmax) -------------------
__global__ void __launch_bounds__(128) flash_kernel(const int* __restrict__ mask) {
    int tid = threadIdx.x;
    int q_s = blockIdx.x * 128 + tid;
    int h = blockIdx.y, b = blockIdx.z;
    const float* base = g_qkv + (size_t)b * S * H3 + (size_t)h * 192;
    const float* qp = base + (size_t)q_s * H3;
    float q[HD];
#pragma unroll
    for (int d = 0; d < HD; d += 4) {
        float4 v = *(const float4*)(qp + d);
        q[d] = v.x * 0.125f; q[d + 1] = v.y * 0.125f;
        q[d + 2] = v.z * 0.125f; q[d + 3] = v.w * 0.125f;
    }
    float acc[HD];
#pragma unroll
    for (int d = 0; d < HD; d++) acc[d] = 0.f;
    float m = -3.4028235e38f, l = 0.f;
    __shared__ float Ks[32][HD];
    __shared__ float Vs[32][HD];
    __shared__ float Ms[32];
    for (int k0 = 0; k0 < S; k0 += 32) {
        for (int i = tid; i < 32 * HD; i += 128) {
            int kk = i >> 6, d = i & 63;
            const float* kp = base + (size_t)(k0 + kk) * H3;
            Ks[kk][d] = kp[64 + d];
            Vs[kk][d] = kp[128 + d];
        }
        if (tid < 32) Ms[tid] = (mask[b * S + k0 + tid] == 0) ? -1.f : 0.f;
        __syncthreads();
        float sc[32];
        float tmax = m;
#pragma unroll 4
        for (int kk = 0; kk < 32; kk++) {
            float s = 0.f;
#pragma unroll
            for (int d = 0; d < HD; d++) s += q[d] * Ks[kk][d];
            s = (Ms[kk] < 0.f) ? -3.4028235e38f : s;
            sc[kk] = s;
            tmax = fmaxf(tmax, s);
        }
        float scale = expf(m - tmax);
        m = tmax;
        l *= scale;
#pragma unroll
        for (int d = 0; d < HD; d++) acc[d] *= scale;
#pragma unroll 4
        for (int kk = 0; kk < 32; kk++) {
            float p = expf(sc[kk] - m);
            l += p;
#pragma unroll
            for (int d = 0; d < HD; d++) acc[d] += p * Vs[kk][d];
        }
        __syncthreads();
    }
    float inv = 1.f / l;
    float* out = g_ctx + (size_t)(b * S + q_s) * H + h * HD;
#pragma unroll
    for (int d = 0; d < HD; d++) out[d] = acc[d] * inv;
}

// ---------------- residual add + RMSNorm -----------------------------------
__global__ void addnorm_kernel(const float* __restrict__ a, const float* __restrict__ bb,
                               const float* __restrict__ w, float* __restrict__ out) {
    __shared__ float buf[H];
    __shared__ float red[8];
    int t = blockIdx.x, tid = threadIdx.x;
    float ss = 0.f;
    for (int d = tid; d < H; d += 256) {
        float v = a[(size_t)t * H + d] + bb[(size_t)t * H + d];
        buf[d] = v;
        ss += v * v;
    }
    for (int o = 16; o; o >>= 1) ss += __shfl_xor_sync(~0u, ss, o);
    if ((tid & 31) == 0) red[tid >> 5] = ss;
    __syncthreads();
    if (tid < 8) {
        float x = red[tid];
        for (int o = 4; o; o >>= 1) x += __shfl_xor_sync(0xffu, x, o);
        if (tid == 0) red[0] = x;
    }
    __syncthreads();
    float inv = rsqrtf(red[0] / (float)H + 1.1920929e-7f);
    for (int d = tid; d < H; d += 256)
        out[(size_t)t * H + d] = buf[d] * inv * w[d];
}

// ---------------- MoE combine (slots) + residual + RMSNorm -----------------
__global__ void moe_combine_norm(const float* __restrict__ w, float* __restrict__ out) {
    __shared__ float buf[H];
    __shared__ float red[8];
    int t = blockIdx.x, tid = threadIdx.x;
    int s0 = g_slot[t * 2], s1 = g_slot[t * 2 + 1];
    float w0 = g_slotw[t * 2], w1v = g_slotw[t * 2 + 1];
    float ss = 0.f;
    for (int d = tid; d < H; d += 256) {
        float v = g_x1[(size_t)t * H + d]
                + w0 * g_ybuf[(size_t)s0 * H + d]
                + w1v * g_ybuf[(size_t)s1 * H + d];
        buf[d] = v;
        ss += v * v;
    }
    for (int o = 16; o; o >>= 1) ss += __shfl_xor_sync(~0u, ss, o);
    if ((tid & 31) == 0) red[tid >> 5] = ss;
    __syncthreads();
    if (tid < 8) {
        float x = red[tid];
        for (int o = 4; o; o >>= 1) x += __shfl_xor_sync(0xffu, x, o);
        if (tid == 0) red[0] = x;
    }
    __syncthreads();
    float inv = rsqrtf(red[0] / (float)H + 1.1920929e-7f);
    for (int d = tid; d < H; d += 256)
        out[(size_t)t * H + d] = buf[d] * inv * w[d];
}

// ---------------- router: logits, softmax, top-2, expert lists -------------
__global__ void router_kernel(const float* __restrict__ gate_w) {
    int warp = threadIdx.x >> 5, lane = threadIdx.x & 31;
    int t = blockIdx.x * 8 + warp;
    float acc[E];
#pragma unroll
    for (int e = 0; e < E; e++) acc[e] = 0.f;
    const float* xr = g_x1 + (size_t)t * H;
    for (int d = lane; d < H; d += 32) {
        float xv = xr[d];
        const float* g = gate_w + (size_t)d * E;
#pragma unroll
        for (int e = 0; e < E; e++) acc[e] += xv * g[e];
    }
#pragma unroll
    for (int e = 0; e < E; e++)
        for (int o = 16; o; o >>= 1) acc[e] += __shfl_xor_sync(~0u, acc[e], o);
    if (lane == 0) {
        float mx = acc[0];
#pragma unroll
        for (int e = 1; e < E; e++) mx = fmaxf(mx, acc[e]);
        float p[E]; float sum = 0.f;
#pragma unroll
        for (int e = 0; e < E; e++) { p[e] = expf(acc[e] - mx); sum += p[e]; }
        float inv = 1.f / sum;
#pragma unroll
        for (int e = 0; e < E; e++) p[e] *= inv;
        int i1 = 0;
#pragma unroll
        for (int e = 1; e < E; e++) if (p[e] > p[i1]) i1 = e;
        int i2 = -1;
#pragma unroll
        for (int e = 0; e < E; e++) {
            if (e == i1) continue;
            if (i2 < 0 || p[e] > p[i2]) i2 = e;
        }
        float s2 = p[i1] + p[i2];
        float w1n = p[i1] / s2, w2n = p[i2] / s2;
        int pos = atomicAdd(&g_cnt[i1], 1);
        g_tok[i1 * T + pos] = t;
        g_slot[t * 2] = i1 * T + pos;
        g_slotw[t * 2] = w1n;
        pos = atomicAdd(&g_cnt[i2], 1);
        g_tok[i2 * T + pos] = t;
        g_slot[t * 2 + 1] = i2 * T + pos;
        g_slotw[t * 2 + 1] = w2n;
#pragma unroll
        for (int e = 0; e < E; e++) atomicAdd(&g_probsum[e], p[e]);
    }
}

__global__ void aux_kernel(float* out) {
    float a = 0.f;
    for (int e = 0; e < E; e++)
        a += ((float)g_cnt[e] / (float)T) * (g_probsum[e] / (float)T);
    out[0] = (float)E * a;
}

// ---------------------------------------------------------------------------
extern "C" void kernel_launch(void* const* d_in, const int* in_sizes, int n_in,
                              void* d_out, int out_size) {
    const float* x      = (const float*)d_in[0];
    const int*   mask   = (const int*)  d_in[1];
    const float* qkv_w  = (const float*)d_in[2];
    const float* out_w  = (const float*)d_in[3];
    const float* gate_w = (const float*)d_in[4];
    const float* w1     = (const float*)d_in[5];
    const float* w2     = (const float*)d_in[6];
    const float* n1     = (const float*)d_in[7];
    const float* n2     = (const float*)d_in[8];
    float* out = (float*)d_out;

    float *p_qkv, *p_ctx, *p_attn, *p_x1, *p_hmid;
    cudaGetSymbolAddress((void**)&p_qkv,  g_qkv);
    cudaGetSymbolAddress((void**)&p_ctx,  g_ctx);
    cudaGetSymbolAddress((void**)&p_attn, g_attn);
    cudaGetSymbolAddress((void**)&p_x1,   g_x1);
    cudaGetSymbolAddress((void**)&p_hmid, g_hmid);

    zero_small<<<1, 32>>>();

    // QKV projection: [T,H] @ [H,3H]
    gemm_tf32<0><<<dim3(H3 / BN, T / BM, 1), 256>>>(x, qkv_w, p_qkv, T, H3, H);

    // RoPE in-place on q,k
    rope_kernel<<<(T * NH * 32 + 255) / 256, 256>>>();

    // attention -> ctx
    flash_kernel<<<dim3(S / 128, NH, B), 128>>>(mask);

    // out projection
    gemm_tf32<0><<<dim3(H / BN, T / BM, 1), 256>>>(p_ctx, out_w, p_attn, T, H, H);

    // x1 = rmsnorm(x + attn_out)
    addnorm_kernel<<<T, 256>>>(x, p_attn, n1, p_x1);

    // router + expert lists
    router_kernel<<<T / 8, 256>>>(gate_w);
    aux_kernel<<<1, 1>>>(out + (size_t)T * H);

    // MoE (only selected experts' tokens), tensor cores
    gemm_tf32<1><<<dim3(F / BN, T / BM, E), 256>>>(p_x1, w1, nullptr, T, F, H);
    gemm_tf32<2><<<dim3(H / BN, T / BM, E), 256>>>(p_hmid, w2, nullptr, T, H, F);

    // x2 = rmsnorm(x1 + moe_out), combining expert slots
    moe_combine_norm<<<T, 256>>>(n2, out);
}

// round 4
// speedup vs baseline: 2.3115x; 1.3169x over previous
#include <cuda_runtime.h>
#include <math.h>

#define B 4
#define S 2048
#define H 768
#define NH 12
#define HD 64
#define E 8
#define TOPK 2
#define F 3072
#define T (B*S)      /* 8192 tokens */
#define H3 (3*H)     /* 2304 */

// ---------------- scratch (device globals: no runtime allocation) ----------
__device__ float g_qkv[(size_t)T*H3];
__device__ float g_ctx[(size_t)T*H];
__device__ float g_attn[(size_t)T*H];
__device__ float g_x1[(size_t)T*H];
__device__ float g_hmid[(size_t)E*T*F];
__device__ float g_ybuf[(size_t)E*T*H];
__device__ int   g_cnt[E];
__device__ float g_probsum[E];
__device__ int   g_tok[E*T];
__device__ int   g_slot[T*TOPK];
__device__ float g_slotw[T*TOPK];

__global__ void zero_small() {
    if (threadIdx.x < E) { g_cnt[threadIdx.x] = 0; g_probsum[threadIdx.x] = 0.f; }
}

__device__ __forceinline__ unsigned f2tf(float x) {
    unsigned u; asm("cvt.rna.tf32.f32 %0, %1;" : "=r"(u) : "f"(x)); return u;
}

#define MMA_TF32(d0,d1,d2,d3,a0,a1,a2,a3,b0,b1) \
    asm volatile("mma.sync.aligned.m16n8k8.row.col.f32.tf32.tf32.f32 " \
                 "{%0,%1,%2,%3},{%4,%5,%6,%7},{%8,%9},{%0,%1,%2,%3};" \
                 : "+f"(d0), "+f"(d1), "+f"(d2), "+f"(d3) \
                 : "r"(a0), "r"(a1), "r"(a2), "r"(a3), "r"(b0), "r"(b1))

// ---------------- tf32 tensor-core GEMM ------------------------------------
#define BM 128
#define BN 128
#define BK 16

template<int MODE>
__global__ void __launch_bounds__(256) gemm_tf32(
    const float* __restrict__ A, const float* __restrict__ W,
    float* __restrict__ Cout, int M, int N, int K)
{
    __shared__ unsigned As[BK][BM + 4];
    __shared__ unsigned Bs[BK][BN + 4];
    __shared__ int rt_s[BM];

    int e = blockIdx.z;
    int c = M;
    int r0 = blockIdx.y * BM;
    if (MODE != 0) {
        c = g_cnt[e];
        if (r0 >= c) return;
    }
    int col0 = blockIdx.x * BN;
    int tid = threadIdx.x;

    const float* Ab = A;
    const float* Wb = W;
    if (MODE == 1) { Wb = W + (size_t)e * K * N; }
    if (MODE == 2) { Ab = A + (size_t)e * T * K; Wb = W + (size_t)e * K * N; }

    if (MODE == 1) {
        if (tid < BM) {
            int r = r0 + tid;
            rt_s[tid] = (r < c) ? g_tok[e * T + r] : -1;
        }
        __syncthreads();
    }

    int lane = tid & 31, warp = tid >> 5;
    int wm = warp >> 2, wn = warp & 3;
    int g = lane >> 2, cq = lane & 3;

    float acc[4][4][4];
#pragma unroll
    for (int i = 0; i < 4; i++)
#pragma unroll
        for (int j = 0; j < 4; j++)
#pragma unroll
            for (int k = 0; k < 4; k++) acc[i][j][k] = 0.f;

    for (int k0 = 0; k0 < K; k0 += BK) {
#pragma unroll
        for (int i = 0; i < 2; i++) {
            int lin = tid + i * 256;
            int r = lin >> 2, kq = (lin & 3) * 4;
            float4 v;
            if (MODE == 0) {
                v = *(const float4*)(Ab + (size_t)(r0 + r) * K + k0 + kq);
            } else if (MODE == 1) {
                int tt = rt_s[r];
                v = (tt >= 0) ? *(const float4*)(Ab + (size_t)tt * K + k0 + kq)
                              : make_float4(0.f, 0.f, 0.f, 0.f);
            } else {
                v = (r0 + r < c) ? *(const float4*)(Ab + (size_t)(r0 + r) * K + k0 + kq)
                                 : make_float4(0.f, 0.f, 0.f, 0.f);
            }
            As[kq + 0][r] = f2tf(v.x);
            As[kq + 1][r] = f2tf(v.y);
            As[kq + 2][r] = f2tf(v.z);
            As[kq + 3][r] = f2tf(v.w);
        }
#pragma unroll
        for (int i = 0; i < 2; i++) {
            int lin = tid + i * 256;
            int r = lin >> 5, nq = (lin & 31) * 4;
            float4 v = *(const float4*)(Wb + (size_t)(k0 + r) * N + col0 + nq);
            Bs[r][nq + 0] = f2tf(v.x);
            Bs[r][nq + 1] = f2tf(v.y);
            Bs[r][nq + 2] = f2tf(v.z);
            Bs[r][nq + 3] = f2tf(v.w);
        }
        __syncthreads();
#pragma unroll
        for (int kk = 0; kk < BK; kk += 8) {
            unsigned a[4][4], b[4][2];
#pragma unroll
            for (int mt = 0; mt < 4; mt++) {
                int m0 = wm * 64 + mt * 16;
                a[mt][0] = As[kk + cq    ][m0 + g    ];
                a[mt][1] = As[kk + cq    ][m0 + g + 8];
                a[mt][2] = As[kk + cq + 4][m0 + g    ];
                a[mt][3] = As[kk + cq + 4][m0 + g + 8];
            }
#pragma unroll
            for (int nt = 0; nt < 4; nt++) {
                int n0 = wn * 32 + nt * 8;
                b[nt][0] = Bs[kk + cq    ][n0 + g];
                b[nt][1] = Bs[kk + cq + 4][n0 + g];
            }
#pragma unroll
            for (int mt = 0; mt < 4; mt++)
#pragma unroll
                for (int nt = 0; nt < 4; nt++) {
                    MMA_TF32(acc[mt][nt][0], acc[mt][nt][1], acc[mt][nt][2], acc[mt][nt][3],
                             a[mt][0], a[mt][1], a[mt][2], a[mt][3],
                             b[nt][0], b[nt][1]);
                }
        }
        __syncthreads();
    }

#pragma unroll
    for (int mt = 0; mt < 4; mt++) {
#pragma unroll
        for (int nt = 0; nt < 4; nt++) {
#pragma unroll
            for (int half = 0; half < 2; half++) {
                int lrow = wm * 64 + mt * 16 + g + half * 8;
                int col = col0 + wn * 32 + nt * 8 + cq * 2;
                float v0 = acc[mt][nt][half * 2 + 0];
                float v1 = acc[mt][nt][half * 2 + 1];
                if (MODE == 0) {
                    Cout[(size_t)(r0 + lrow) * N + col]     = v0;
                    Cout[(size_t)(r0 + lrow) * N + col + 1] = v1;
                } else if (MODE == 1) {
                    int r = r0 + lrow;
                    if (r < c) {
                        float g0 = 0.5f * v0 * (1.f + erff(v0 * 0.70710678118f));
                        float g1 = 0.5f * v1 * (1.f + erff(v1 * 0.70710678118f));
                        g_hmid[((size_t)e * T + r) * F + col]     = g0;
                        g_hmid[((size_t)e * T + r) * F + col + 1] = g1;
                    }
                } else {
                    int r = r0 + lrow;
                    if (r < c) {
                        g_ybuf[((size_t)e * T + r) * H + col]     = v0;
                        g_ybuf[((size_t)e * T + r) * H + col + 1] = v1;
                    }
                }
            }
        }
    }
}

// ---------------- RoPE applied in-place to q,k inside g_qkv ----------------
__global__ void rope_kernel() {
    int idx = blockIdx.x * blockDim.x + threadIdx.x;
    if (idx >= T * NH * 32) return;
    int i = idx & 31;
    int h = (idx >> 5) % NH;
    int t = idx / (32 * NH);
    int s = t % S;
    float invf = expf(-(float)i * (9.210340371976184f / 32.f));
    float th = (float)s * invf;
    float c = cosf(th), sn = sinf(th);
    float* p = g_qkv + (size_t)t * H3 + h * 192;
    float q1 = p[i], q2 = p[i + 32];
    p[i]      = q1 * c - q2 * sn;
    p[i + 32] = q2 * c + q1 * sn;
    float k1 = p[64 + i], k2 = p[64 + i + 32];
    p[64 + i]      = k1 * c - k2 * sn;
    p[64 + i + 32] = k2 * c + k1 * sn;
}

// ---------------- flash attention v2: tensor-core QK^T and PV --------------
// grid (S/64, NH, B), 128 threads (4 warps x 16 query rows).
// smem: Qs[64][68] tf32, Ks[64][68] tf32, Vs[64][72] tf32, Mk[64] float.
#define QS_STRIDE 68
#define VS_STRIDE 72
#define FLASH_SMEM ((64*QS_STRIDE*2 + 64*VS_STRIDE) * 4 + 64 * 4)

__global__ void __launch_bounds__(128) flash2_kernel(const int* __restrict__ mask) {
    extern __shared__ unsigned smem[];
    unsigned* Qs = smem;                       // [64][68]
    unsigned* Ks = Qs + 64 * QS_STRIDE;        // [64][68]
    unsigned* Vs = Ks + 64 * QS_STRIDE;        // [64][72]
    float*    Mk = (float*)(Vs + 64 * VS_STRIDE);

    int tid = threadIdx.x;
    int lane = tid & 31, warp = tid >> 5;
    int g = lane >> 2, cq = lane & 3;
    int q0 = blockIdx.x * 64, h = blockIdx.y, b = blockIdx.z;
    const float* base = g_qkv + (size_t)b * S * H3 + (size_t)h * 192;

    // load Q tile (scaled by 1/8), tf32
    {
        int r = tid >> 1, c0 = (tid & 1) * 32;
        const float* qp = base + (size_t)(q0 + r) * H3 + c0;
#pragma unroll
        for (int j = 0; j < 8; j++) {
            float4 v = *(const float4*)(qp + j * 4);
            unsigned* dst = Qs + r * QS_STRIDE + c0 + j * 4;
            dst[0] = f2tf(v.x * 0.125f); dst[1] = f2tf(v.y * 0.125f);
            dst[2] = f2tf(v.z * 0.125f); dst[3] = f2tf(v.w * 0.125f);
        }
    }

    float acc_o[8][4];
#pragma unroll
    for (int nt = 0; nt < 8; nt++)
#pragma unroll
        for (int j = 0; j < 4; j++) acc_o[nt][j] = 0.f;
    float m0r = -1e30f, m1r = -1e30f, l0 = 0.f, l1 = 0.f;

    int m0 = warp * 16;
    unsigned fullm = 0xffffffffu;
    int qbase = lane & ~3;

    for (int k0 = 0; k0 < S; k0 += 64) {
        __syncthreads();
        // load K, V tiles
        {
            int r = tid >> 1, c0 = (tid & 1) * 32;
            const float* kp = base + (size_t)(k0 + r) * H3 + c0;
#pragma unroll
            for (int j = 0; j < 8; j++) {
                float4 kv = *(const float4*)(kp + 64 + j * 4);
                unsigned* kd = Ks + r * QS_STRIDE + c0 + j * 4;
                kd[0] = f2tf(kv.x); kd[1] = f2tf(kv.y);
                kd[2] = f2tf(kv.z); kd[3] = f2tf(kv.w);
                float4 vv = *(const float4*)(kp + 128 + j * 4);
                unsigned* vd = Vs + r * VS_STRIDE + c0 + j * 4;
                vd[0] = f2tf(vv.x); vd[1] = f2tf(vv.y);
                vd[2] = f2tf(vv.z); vd[3] = f2tf(vv.w);
            }
        }
        if (tid < 64) Mk[tid] = (mask[b * S + k0 + tid] == 0) ? -1e30f : 0.f;
        __syncthreads();

        // ---- S = Q K^T (16x64 per warp) ----
        float sacc[8][4];
#pragma unroll
        for (int nt = 0; nt < 8; nt++)
#pragma unroll
            for (int j = 0; j < 4; j++) sacc[nt][j] = 0.f;
#pragma unroll
        for (int kk = 0; kk < 64; kk += 8) {
            unsigned a0 = Qs[(m0 + g    ) * QS_STRIDE + kk + cq    ];
            unsigned a1 = Qs[(m0 + g + 8) * QS_STRIDE + kk + cq    ];
            unsigned a2 = Qs[(m0 + g    ) * QS_STRIDE + kk + cq + 4];
            unsigned a3 = Qs[(m0 + g + 8) * QS_STRIDE + kk + cq + 4];
#pragma unroll
            for (int nt = 0; nt < 8; nt++) {
                unsigned b0 = Ks[(nt * 8 + g) * QS_STRIDE + kk + cq    ];
                unsigned b1 = Ks[(nt * 8 + g) * QS_STRIDE + kk + cq + 4];
                MMA_TF32(sacc[nt][0], sacc[nt][1], sacc[nt][2], sacc[nt][3],
                         a0, a1, a2, a3, b0, b1);
            }
        }

        // ---- mask + online softmax ----
        float mx0 = -1e30f, mx1 = -1e30f;
#pragma unroll
        for (int nt = 0; nt < 8; nt++) {
            float mk0 = Mk[nt * 8 + cq * 2], mk1 = Mk[nt * 8 + cq * 2 + 1];
            sacc[nt][0] += mk0; sacc[nt][1] += mk1;
            sacc[nt][2] += mk0; sacc[nt][3] += mk1;
            mx0 = fmaxf(mx0, fmaxf(sacc[nt][0], sacc[nt][1]));
            mx1 = fmaxf(mx1, fmaxf(sacc[nt][2], sacc[nt][3]));
        }
        mx0 = fmaxf(mx0, __shfl_xor_sync(fullm, mx0, 1));
        mx0 = fmaxf(mx0, __shfl_xor_sync(fullm, mx0, 2));
        mx1 = fmaxf(mx1, __shfl_xor_sync(fullm, mx1, 1));
        mx1 = fmaxf(mx1, __shfl_xor_sync(fullm, mx1, 2));
        float newm0 = fmaxf(m0r, mx0), newm1 = fmaxf(m1r, mx1);
        float sc0 = __expf(m0r - newm0), sc1 = __expf(m1r - newm1);
        m0r = newm0; m1r = newm1;
        float ps0 = 0.f, ps1 = 0.f;
#pragma unroll
        for (int nt = 0; nt < 8; nt++) {
            sacc[nt][0] = __expf(sacc[nt][0] - newm0);
            sacc[nt][1] = __expf(sacc[nt][1] - newm0);
            sacc[nt][2] = __expf(sacc[nt][2] - newm1);
            sacc[nt][3] = __expf(sacc[nt][3] - newm1);
            ps0 += sacc[nt][0] + sacc[nt][1];
            ps1 += sacc[nt][2] + sacc[nt][3];
            acc_o[nt][0] *= sc0; acc_o[nt][1] *= sc0;
            acc_o[nt][2] *= sc1; acc_o[nt][3] *= sc1;
        }
        ps0 += __shfl_xor_sync(fullm, ps0, 1); ps0 += __shfl_xor_sync(fullm, ps0, 2);
        ps1 += __shfl_xor_sync(fullm, ps1, 1); ps1 += __shfl_xor_sync(fullm, ps1, 2);
        l0 = l0 * sc0 + ps0;
        l1 = l1 * sc1 + ps1;

        // ---- O += P V ----
        int s_lo = qbase + (cq >> 1);
        int s_hi = qbase + 2 + (cq >> 1);
        bool odd = (cq & 1);
#pragma unroll
        for (int kt = 0; kt < 8; kt++) {
            unsigned p0 = f2tf(sacc[kt][0]), p1 = f2tf(sacc[kt][1]);
            unsigned p2 = f2tf(sacc[kt][2]), p3 = f2tf(sacc[kt][3]);
            unsigned u0 = __shfl_sync(fullm, p0, s_lo), u1 = __shfl_sync(fullm, p1, s_lo);
            unsigned a0 = odd ? u1 : u0;
            unsigned w0 = __shfl_sync(fullm, p2, s_lo), w1 = __shfl_sync(fullm, p3, s_lo);
            unsigned a1 = odd ? w1 : w0;
            unsigned v0 = __shfl_sync(fullm, p0, s_hi), v1 = __shfl_sync(fullm, p1, s_hi);
            unsigned a2 = odd ? v1 : v0;
            unsigned x0 = __shfl_sync(fullm, p2, s_hi), x1 = __shfl_sync(fullm, p3, s_hi);
            unsigned a3 = odd ? x1 : x0;
#pragma unroll
            for (int nt = 0; nt < 8; nt++) {
                unsigned b0 = Vs[(kt * 8 + cq    ) * VS_STRIDE + nt * 8 + g];
                unsigned b1 = Vs[(kt * 8 + cq + 4) * VS_STRIDE + nt * 8 + g];
                MMA_TF32(acc_o[nt][0], acc_o[nt][1], acc_o[nt][2], acc_o[nt][3],
                         a0, a1, a2, a3, b0, b1);
            }
        }
    }

    // ---- epilogue ----
    float inv0 = 1.f / l0, inv1 = 1.f / l1;
    size_t row0 = (size_t)(b * S + q0 + m0 + g) * H + h * HD;
    size_t row1 = row0 + (size_t)8 * H;
#pragma unroll
    for (int nt = 0; nt < 8; nt++) {
        int col = nt * 8 + cq * 2;
        g_ctx[row0 + col]     = acc_o[nt][0] * inv0;
        g_ctx[row0 + col + 1] = acc_o[nt][1] * inv0;
        g_ctx[row1 + col]     = acc_o[nt][2] * inv1;
        g_ctx[row1 + col + 1] = acc_o[nt][3] * inv1;
    }
}

// ---------------- residual add + RMSNorm -----------------------------------
__global__ void addnorm_kernel(const float* __restrict__ a, const float* __restrict__ bb,
                               const float* __restrict__ w, float* __restrict__ out) {
    __shared__ float buf[H];
    __shared__ float red[8];
    int t = blockIdx.x, tid = threadIdx.x;
    float ss = 0.f;
    for (int d = tid; d < H; d += 256) {
        float v = a[(size_t)t * H + d] + bb[(size_t)t * H + d];
        buf[d] = v;
        ss += v * v;
    }
    for (int o = 16; o; o >>= 1) ss += __shfl_xor_sync(~0u, ss, o);
    if ((tid & 31) == 0) red[tid >> 5] = ss;
    __syncthreads();
    if (tid < 8) {
        float x = red[tid];
        for (int o = 4; o; o >>= 1) x += __shfl_xor_sync(0xffu, x, o);
        if (tid == 0) red[0] = x;
    }
    __syncthreads();
    float inv = rsqrtf(red[0] / (float)H + 1.1920929e-7f);
    for (int d = tid; d < H; d += 256)
        out[(size_t)t * H + d] = buf[d] * inv * w[d];
}

// ---------------- MoE combine (slots) + residual + RMSNorm -----------------
__global__ void moe_combine_norm(const float* __restrict__ w, float* __restrict__ out) {
    __shared__ float buf[H];
    __shared__ float red[8];
    int t = blockIdx.x, tid = threadIdx.x;
    int s0 = g_slot[t * 2], s1 = g_slot[t * 2 + 1];
    float w0 = g_slotw[t * 2], w1v = g_slotw[t * 2 + 1];
    float ss = 0.f;
    for (int d = tid; d < H; d += 256) {
        float v = g_x1[(size_t)t * H + d]
                + w0 * g_ybuf[(size_t)s0 * H + d]
                + w1v * g_ybuf[(size_t)s1 * H + d];
        buf[d] = v;
        ss += v * v;
    }
    for (int o = 16; o; o >>= 1) ss += __shfl_xor_sync(~0u, ss, o);
    if ((tid & 31) == 0) red[tid >> 5] = ss;
    __syncthreads();
    if (tid < 8) {
        float x = red[tid];
        for (int o = 4; o; o >>= 1) x += __shfl_xor_sync(0xffu, x, o);
        if (tid == 0) red[0] = x;
    }
    __syncthreads();
    float inv = rsqrtf(red[0] / (float)H + 1.1920929e-7f);
    for (int d = tid; d < H; d += 256)
        out[(size_t)t * H + d] = buf[d] * inv * w[d];
}

// ---------------- router -----------------------------------------------------
__global__ void router_kernel(const float* __restrict__ gate_w) {
    int warp = threadIdx.x >> 5, lane = threadIdx.x & 31;
    int t = blockIdx.x * 8 + warp;
    float acc[E];
#pragma unroll
    for (int e = 0; e < E; e++) acc[e] = 0.f;
    const float* xr = g_x1 + (size_t)t * H;
    for (int d = lane; d < H; d += 32) {
        float xv = xr[d];
        const float* g = gate_w + (size_t)d * E;
#pragma unroll
        for (int e = 0; e < E; e++) acc[e] += xv * g[e];
    }
#pragma unroll
    for (int e = 0; e < E; e++)
        for (int o = 16; o; o >>= 1) acc[e] += __shfl_xor_sync(~0u, acc[e], o);
    if (lane == 0) {
        float mx = acc[0];
#pragma unroll
        for (int e = 1; e < E; e++) mx = fmaxf(mx, acc[e]);
        float p[E]; float sum = 0.f;
#pragma unroll
        for (int e = 0; e < E; e++) { p[e] = expf(acc[e] - mx); sum += p[e]; }
        float inv = 1.f / sum;
#pragma unroll
        for (int e = 0; e < E; e++) p[e] *= inv;
        int i1 = 0;
#pragma unroll
        for (int e = 1; e < E; e++) if (p[e] > p[i1]) i1 = e;
        int i2 = -1;
#pragma unroll
        for (int e = 0; e < E; e++) {
            if (e == i1) continue;
            if (i2 < 0 || p[e] > p[i2]) i2 = e;
        }
        float s2 = p[i1] + p[i2];
        float w1n = p[i1] / s2, w2n = p[i2] / s2;
        int pos = atomicAdd(&g_cnt[i1], 1);
        g_tok[i1 * T + pos] = t;
        g_slot[t * 2] = i1 * T + pos;
        g_slotw[t * 2] = w1n;
        pos = atomicAdd(&g_cnt[i2], 1);
        g_tok[i2 * T + pos] = t;
        g_slot[t * 2 + 1] = i2 * T + pos;
        g_slotw[t * 2 + 1] = w2n;
#pragma unroll
        for (int e = 0; e < E; e++) atomicAdd(&g_probsum[e], p[e]);
    }
}

__global__ void aux_kernel(float* out) {
    float a = 0.f;
    for (int e = 0; e < E; e++)
        a += ((float)g_cnt[e] / (float)T) * (g_probsum[e] / (float)T);
    out[0] = (float)E * a;
}

// ---------------------------------------------------------------------------
extern "C" void kernel_launch(void* const* d_in, const int* in_sizes, int n_in,
                              void* d_out, int out_size) {
    const float* x      = (const float*)d_in[0];
    const int*   mask   = (const int*)  d_in[1];
    const float* qkv_w  = (const float*)d_in[2];
    const float* out_w  = (const float*)d_in[3];
    const float* gate_w = (const float*)d_in[4];
    const float* w1     = (const float*)d_in[5];
    const float* w2     = (const float*)d_in[6];
    const float* n1     = (const float*)d_in[7];
    const float* n2     = (const float*)d_in[8];
    float* out = (float*)d_out;

    float *p_qkv, *p_ctx, *p_attn, *p_x1, *p_hmid;
    cudaGetSymbolAddress((void**)&p_qkv,  g_qkv);
    cudaGetSymbolAddress((void**)&p_ctx,  g_ctx);
    cudaGetSymbolAddress((void**)&p_attn, g_attn);
    cudaGetSymbolAddress((void**)&p_x1,   g_x1);
    cudaGetSymbolAddress((void**)&p_hmid, g_hmid);

    static bool attr_set = false;
    if (!attr_set) {
        cudaFuncSetAttribute(flash2_kernel,
                             cudaFuncAttributeMaxDynamicSharedMemorySize, FLASH_SMEM);
        attr_set = true;
    }

    zero_small<<<1, 32>>>();

    gemm_tf32<0><<<dim3(H3 / BN, T / BM, 1), 256>>>(x, qkv_w, p_qkv, T, H3, H);

    rope_kernel<<<(T * NH * 32 + 255) / 256, 256>>>();

    flash2_kernel<<<dim3(S / 64, NH, B), 128, FLASH_SMEM>>>(mask);

    gemm_tf32<0><<<dim3(H / BN, T / BM, 1), 256>>>(p_ctx, out_w, p_attn, T, H, H);

    addnorm_kernel<<<T, 256>>>(x, p_attn, n1, p_x1);

    router_kernel<<<T / 8, 256>>>(gate_w);
    aux_kernel<<<1, 1>>>(out + (size_t)T * H);

    gemm_tf32<1><<<dim3(F / BN, T / BM, E), 256>>>(p_x1, w1, nullptr, T, F, H);
    gemm_tf32<2><<<dim3(H / BN, T / BM, E), 256>>>(p_hmid, w2, nullptr, T, H, F);

    moe_combine_norm<<<T, 256>>>(n2, out);
}

// round 5
// speedup vs baseline: 2.5323x; 1.0955x over previous
#include <cuda_runtime.h>
#include <math.h>

#define B 4
#define S 2048
#define H 768
#define NH 12
#define HD 64
#define E 8
#define TOPK 2
#define F 3072
#define T (B*S)      /* 8192 tokens */
#define H3 (3*H)     /* 2304 */

// ---------------- scratch (device globals: no runtime allocation) ----------
__device__ float g_qkv[(size_t)T*H3];
__device__ float g_ctx[(size_t)T*H];
__device__ float g_attn[(size_t)T*H];
__device__ float g_x1[(size_t)T*H];
__device__ float g_hmid[(size_t)E*T*F];
__device__ float g_ybuf[(size_t)E*T*H];
__device__ int   g_cnt[E];
__device__ float g_probsum[E];
__device__ int   g_tok[E*T];
__device__ int   g_slot[T*TOPK];
__device__ float g_slotw[T*TOPK];

__global__ void zero_small() {
    if (threadIdx.x < E) { g_cnt[threadIdx.x] = 0; g_probsum[threadIdx.x] = 0.f; }
}

__device__ __forceinline__ unsigned f2tf(float x) {
    unsigned u; asm("cvt.rna.tf32.f32 %0, %1;" : "=r"(u) : "f"(x)); return u;
}

#define MMA_TF32(d0,d1,d2,d3,a0,a1,a2,a3,b0,b1) \
    asm volatile("mma.sync.aligned.m16n8k8.row.col.f32.tf32.tf32.f32 " \
                 "{%0,%1,%2,%3},{%4,%5,%6,%7},{%8,%9},{%0,%1,%2,%3};" \
                 : "+f"(d0), "+f"(d1), "+f"(d2), "+f"(d3) \
                 : "r"(a0), "r"(a1), "r"(a2), "r"(a3), "r"(b0), "r"(b1))

__device__ __forceinline__ void cp_async16(void* smem_dst, const void* gsrc) {
    unsigned saddr = (unsigned)__cvta_generic_to_shared(smem_dst);
    asm volatile("cp.async.ca.shared.global [%0], [%1], 16;" :: "r"(saddr), "l"(gsrc));
}
#define CP_COMMIT asm volatile("cp.async.commit_group;")
#define CP_WAIT0  asm volatile("cp.async.wait_group 0;")

// ---------------- tf32 tensor-core GEMM, 2-stage cp.async pipeline ---------
#define BM 128
#define BN 128
#define BK 16

template<int MODE>
__global__ void __launch_bounds__(256) gemm_tf32(
    const float* __restrict__ A, const float* __restrict__ W,
    float* __restrict__ Cout, int M, int N, int K)
{
    __shared__ unsigned As[2][BK][BM + 4];
    __shared__ float    Bs[2][BK][BN + 4];
    __shared__ int rt_s[BM];

    int e = blockIdx.z;
    int c = M;
    int r0 = blockIdx.y * BM;
    if (MODE != 0) {
        c = g_cnt[e];
        if (r0 >= c) return;
    }
    int col0 = blockIdx.x * BN;
    int tid = threadIdx.x;

    const float* Ab = A;
    const float* Wb = W;
    if (MODE == 1) { Wb = W + (size_t)e * K * N; }
    if (MODE == 2) { Ab = A + (size_t)e * T * K; Wb = W + (size_t)e * K * N; }

    if (MODE == 1) {
        if (tid < BM) {
            int r = r0 + tid;
            rt_s[tid] = (r < c) ? g_tok[e * T + r] : -1;
        }
        __syncthreads();
    }

    int lane = tid & 31, warp = tid >> 5;
    int wm = warp >> 2, wn = warp & 3;
    int g = lane >> 2, cq = lane & 3;

    float4 areg[2];
    int ar_[2], akq_[2];
#pragma unroll
    for (int i = 0; i < 2; i++) {
        int lin = tid + i * 256;
        ar_[i] = lin >> 2;
        akq_[i] = (lin & 3) * 4;
    }

    auto loadA = [&](int k0) {
#pragma unroll
        for (int i = 0; i < 2; i++) {
            int r = ar_[i], kq = akq_[i];
            if (MODE == 0) {
                areg[i] = *(const float4*)(Ab + (size_t)(r0 + r) * K + k0 + kq);
            } else if (MODE == 1) {
                int tt = rt_s[r];
                areg[i] = (tt >= 0) ? *(const float4*)(Ab + (size_t)tt * K + k0 + kq)
                                    : make_float4(0.f, 0.f, 0.f, 0.f);
            } else {
                areg[i] = (r0 + r < c) ? *(const float4*)(Ab + (size_t)(r0 + r) * K + k0 + kq)
                                       : make_float4(0.f, 0.f, 0.f, 0.f);
            }
        }
    };
    auto storeA = [&](int buf) {
#pragma unroll
        for (int i = 0; i < 2; i++) {
            int r = ar_[i], kq = akq_[i];
            As[buf][kq + 0][r] = f2tf(areg[i].x);
            As[buf][kq + 1][r] = f2tf(areg[i].y);
            As[buf][kq + 2][r] = f2tf(areg[i].z);
            As[buf][kq + 3][r] = f2tf(areg[i].w);
        }
    };
    auto issueB = [&](int buf, int k0) {
#pragma unroll
        for (int i = 0; i < 2; i++) {
            int lin = tid + i * 256;
            int r = lin >> 5, nq = (lin & 31) * 4;
            cp_async16(&Bs[buf][r][nq], Wb + (size_t)(k0 + r) * N + col0 + nq);
        }
    };

    float acc[4][4][4];
#pragma unroll
    for (int i = 0; i < 4; i++)
#pragma unroll
        for (int j = 0; j < 4; j++)
#pragma unroll
            for (int k = 0; k < 4; k++) acc[i][j][k] = 0.f;

    int nIter = K / BK;
    loadA(0);
    issueB(0, 0);
    CP_COMMIT;
    int cur = 0;

    for (int it = 0; it < nIter; it++) {
        storeA(cur);
        CP_WAIT0;
        __syncthreads();
        if (it + 1 < nIter) {
            loadA((it + 1) * BK);
            issueB(cur ^ 1, (it + 1) * BK);
            CP_COMMIT;
        }
#pragma unroll
        for (int kk = 0; kk < BK; kk += 8) {
            unsigned a[4][4], b[4][2];
#pragma unroll
            for (int mt = 0; mt < 4; mt++) {
                int m0 = wm * 64 + mt * 16;
                a[mt][0] = As[cur][kk + cq    ][m0 + g    ];
                a[mt][1] = As[cur][kk + cq    ][m0 + g + 8];
                a[mt][2] = As[cur][kk + cq + 4][m0 + g    ];
                a[mt][3] = As[cur][kk + cq + 4][m0 + g + 8];
            }
#pragma unroll
            for (int nt = 0; nt < 4; nt++) {
                int n0 = wn * 32 + nt * 8;
                b[nt][0] = f2tf(Bs[cur][kk + cq    ][n0 + g]);
                b[nt][1] = f2tf(Bs[cur][kk + cq + 4][n0 + g]);
            }
#pragma unroll
            for (int mt = 0; mt < 4; mt++)
#pragma unroll
                for (int nt = 0; nt < 4; nt++) {
                    MMA_TF32(acc[mt][nt][0], acc[mt][nt][1], acc[mt][nt][2], acc[mt][nt][3],
                             a[mt][0], a[mt][1], a[mt][2], a[mt][3],
                             b[nt][0], b[nt][1]);
                }
        }
        cur ^= 1;
    }

#pragma unroll
    for (int mt = 0; mt < 4; mt++) {
#pragma unroll
        for (int nt = 0; nt < 4; nt++) {
#pragma unroll
            for (int half = 0; half < 2; half++) {
                int lrow = wm * 64 + mt * 16 + g + half * 8;
                int col = col0 + wn * 32 + nt * 8 + cq * 2;
                float v0 = acc[mt][nt][half * 2 + 0];
                float v1 = acc[mt][nt][half * 2 + 1];
                if (MODE == 0) {
                    Cout[(size_t)(r0 + lrow) * N + col]     = v0;
                    Cout[(size_t)(r0 + lrow) * N + col + 1] = v1;
                } else if (MODE == 1) {
                    int r = r0 + lrow;
                    if (r < c) {
                        float g0 = 0.5f * v0 * (1.f + erff(v0 * 0.70710678118f));
                        float g1 = 0.5f * v1 * (1.f + erff(v1 * 0.70710678118f));
                        g_hmid[((size_t)e * T + r) * F + col]     = g0;
                        g_hmid[((size_t)e * T + r) * F + col + 1] = g1;
                    }
                } else {
                    int r = r0 + lrow;
                    if (r < c) {
                        g_ybuf[((size_t)e * T + r) * H + col]     = v0;
                        g_ybuf[((size_t)e * T + r) * H + col + 1] = v1;
                    }
                }
            }
        }
    }
}

// ---------------- RoPE applied in-place to q,k inside g_qkv ----------------
__global__ void rope_kernel() {
    int idx = blockIdx.x * blockDim.x + threadIdx.x;
    if (idx >= T * NH * 32) return;
    int i = idx & 31;
    int h = (idx >> 5) % NH;
    int t = idx / (32 * NH);
    int s = t % S;
    float invf = expf(-(float)i * (9.210340371976184f / 32.f));
    float th = (float)s * invf;
    float c = cosf(th), sn = sinf(th);
    float* p = g_qkv + (size_t)t * H3 + h * 192;
    float q1 = p[i], q2 = p[i + 32];
    p[i]      = q1 * c - q2 * sn;
    p[i + 32] = q2 * c + q1 * sn;
    float k1 = p[64 + i], k2 = p[64 + i + 32];
    p[64 + i]      = k1 * c - k2 * sn;
    p[64 + i + 32] = k2 * c + k1 * sn;
}

// ---------------- flash attention v3: Q in regs, cp.async K/V pipeline -----
// grid (S/64, NH, B), 128 threads (4 warps x 16 query rows).
#define KS_STRIDE 68
#define VS_STRIDE 72
#define FLASH_SMEM ((2*64*KS_STRIDE + 2*64*VS_STRIDE) * 4 + 2 * 64 * 4)

__global__ void __launch_bounds__(128) flash3_kernel(const int* __restrict__ mask) {
    extern __shared__ float fsm[];
    float* KsB = fsm;                          // [2][64][68]
    float* VsB = KsB + 2 * 64 * KS_STRIDE;     // [2][64][72]
    int*   MkB = (int*)(VsB + 2 * 64 * VS_STRIDE); // [2][64]

    int tid = threadIdx.x;
    int lane = tid & 31, warp = tid >> 5;
    int g = lane >> 2, cq = lane & 3;
    int q0 = blockIdx.x * 64, h = blockIdx.y, b = blockIdx.z;
    const float* base = g_qkv + (size_t)b * S * H3 + (size_t)h * 192;
    int m0 = warp * 16;

    // ---- Q fragments in registers (scaled, tf32) ----
    unsigned qf[8][4];
    {
        const float* qr0 = base + (size_t)(q0 + m0 + g) * H3;
        const float* qr1 = qr0 + (size_t)8 * H3;
#pragma unroll
        for (int cc = 0; cc < 8; cc++) {
            qf[cc][0] = f2tf(qr0[cc * 8 + cq]     * 0.125f);
            qf[cc][1] = f2tf(qr1[cc * 8 + cq]     * 0.125f);
            qf[cc][2] = f2tf(qr0[cc * 8 + cq + 4] * 0.125f);
            qf[cc][3] = f2tf(qr1[cc * 8 + cq + 4] * 0.125f);
        }
    }

    // cp.async issue for one K/V/mask tile
    int lr = tid >> 1, lc = (tid & 1) * 32;
    auto issueKV = [&](int buf, int k0) {
        const float* kp = base + (size_t)(k0 + lr) * H3;
        float* kd = KsB + buf * 64 * KS_STRIDE + lr * KS_STRIDE + lc;
        float* vd = VsB + buf * 64 * VS_STRIDE + lr * VS_STRIDE + lc;
#pragma unroll
        for (int j = 0; j < 8; j++) {
            cp_async16(kd + j * 4, kp + 64  + lc + j * 4);
            cp_async16(vd + j * 4, kp + 128 + lc + j * 4);
        }
        if (tid < 16)
            cp_async16(MkB + buf * 64 + tid * 4, mask + b * S + k0 + tid * 4);
    };

    float acc_o[8][4];
#pragma unroll
    for (int nt = 0; nt < 8; nt++)
#pragma unroll
        for (int j = 0; j < 4; j++) acc_o[nt][j] = 0.f;
    float m0r = -1e30f, m1r = -1e30f, l0 = 0.f, l1 = 0.f;

    unsigned fullm = 0xffffffffu;
    int qbase = lane & ~3;

    issueKV(0, 0);
    CP_COMMIT;
    int cur = 0;

    for (int k0 = 0; k0 < S; k0 += 64) {
        CP_WAIT0;
        __syncthreads();
        if (k0 + 64 < S) {
            issueKV(cur ^ 1, k0 + 64);
            CP_COMMIT;
        }
        const float* Kc = KsB + cur * 64 * KS_STRIDE;
        const float* Vc = VsB + cur * 64 * VS_STRIDE;
        const int*   Mc = MkB + cur * 64;

        // ---- S = Q K^T (16x64 per warp) ----
        float sacc[8][4];
#pragma unroll
        for (int nt = 0; nt < 8; nt++)
#pragma unroll
            for (int j = 0; j < 4; j++) sacc[nt][j] = 0.f;
#pragma unroll
        for (int kk = 0; kk < 64; kk += 8) {
            int cc = kk >> 3;
#pragma unroll
            for (int nt = 0; nt < 8; nt++) {
                unsigned b0 = f2tf(Kc[(nt * 8 + g) * KS_STRIDE + kk + cq    ]);
                unsigned b1 = f2tf(Kc[(nt * 8 + g) * KS_STRIDE + kk + cq + 4]);
                MMA_TF32(sacc[nt][0], sacc[nt][1], sacc[nt][2], sacc[nt][3],
                         qf[cc][0], qf[cc][1], qf[cc][2], qf[cc][3], b0, b1);
            }
        }

        // ---- mask + online softmax ----
        float mx0 = -1e30f, mx1 = -1e30f;
#pragma unroll
        for (int nt = 0; nt < 8; nt++) {
            float mk0 = (Mc[nt * 8 + cq * 2]     == 0) ? -1e30f : 0.f;
            float mk1 = (Mc[nt * 8 + cq * 2 + 1] == 0) ? -1e30f : 0.f;
            sacc[nt][0] += mk0; sacc[nt][1] += mk1;
            sacc[nt][2] += mk0; sacc[nt][3] += mk1;
            mx0 = fmaxf(mx0, fmaxf(sacc[nt][0], sacc[nt][1]));
            mx1 = fmaxf(mx1, fmaxf(sacc[nt][2], sacc[nt][3]));
        }
        mx0 = fmaxf(mx0, __shfl_xor_sync(fullm, mx0, 1));
        mx0 = fmaxf(mx0, __shfl_xor_sync(fullm, mx0, 2));
        mx1 = fmaxf(mx1, __shfl_xor_sync(fullm, mx1, 1));
        mx1 = fmaxf(mx1, __shfl_xor_sync(fullm, mx1, 2));
        float newm0 = fmaxf(m0r, mx0), newm1 = fmaxf(m1r, mx1);
        float sc0 = __expf(m0r - newm0), sc1 = __expf(m1r - newm1);
        m0r = newm0; m1r = newm1;
        float ps0 = 0.f, ps1 = 0.f;
#pragma unroll
        for (int nt = 0; nt < 8; nt++) {
            sacc[nt][0] = __expf(sacc[nt][0] - newm0);
            sacc[nt][1] = __expf(sacc[nt][1] - newm0);
            sacc[nt][2] = __expf(sacc[nt][2] - newm1);
            sacc[nt][3] = __expf(sacc[nt][3] - newm1);
            ps0 += sacc[nt][0] + sacc[nt][1];
            ps1 += sacc[nt][2] + sacc[nt][3];
            acc_o[nt][0] *= sc0; acc_o[nt][1] *= sc0;
            acc_o[nt][2] *= sc1; acc_o[nt][3] *= sc1;
        }
        ps0 += __shfl_xor_sync(fullm, ps0, 1); ps0 += __shfl_xor_sync(fullm, ps0, 2);
        ps1 += __shfl_xor_sync(fullm, ps1, 1); ps1 += __shfl_xor_sync(fullm, ps1, 2);
        l0 = l0 * sc0 + ps0;
        l1 = l1 * sc1 + ps1;

        // ---- O += P V ----
        int s_lo = qbase + (cq >> 1);
        int s_hi = qbase + 2 + (cq >> 1);
        bool odd = (cq & 1);
#pragma unroll
        for (int kt = 0; kt < 8; kt++) {
            unsigned p0 = f2tf(sacc[kt][0]), p1 = f2tf(sacc[kt][1]);
            unsigned p2 = f2tf(sacc[kt][2]), p3 = f2tf(sacc[kt][3]);
            unsigned u0 = __shfl_sync(fullm, p0, s_lo), u1 = __shfl_sync(fullm, p1, s_lo);
            unsigned a0 = odd ? u1 : u0;
            unsigned w0 = __shfl_sync(fullm, p2, s_lo), w1 = __shfl_sync(fullm, p3, s_lo);
            unsigned a1 = odd ? w1 : w0;
            unsigned v0 = __shfl_sync(fullm, p0, s_hi), v1 = __shfl_sync(fullm, p1, s_hi);
            unsigned a2 = odd ? v1 : v0;
            unsigned x0 = __shfl_sync(fullm, p2, s_hi), x1 = __shfl_sync(fullm, p3, s_hi);
            unsigned a3 = odd ? x1 : x0;
#pragma unroll
            for (int nt = 0; nt < 8; nt++) {
                unsigned b0 = f2tf(Vc[(kt * 8 + cq    ) * VS_STRIDE + nt * 8 + g]);
                unsigned b1 = f2tf(Vc[(kt * 8 + cq + 4) * VS_STRIDE + nt * 8 + g]);
                MMA_TF32(acc_o[nt][0], acc_o[nt][1], acc_o[nt][2], acc_o[nt][3],
                         a0, a1, a2, a3, b0, b1);
            }
        }
        cur ^= 1;
    }

    // ---- epilogue ----
    float inv0 = 1.f / l0, inv1 = 1.f / l1;
    size_t row0 = (size_t)(b * S + q0 + m0 + g) * H + h * HD;
    size_t row1 = row0 + (size_t)8 * H;
#pragma unroll
    for (int nt = 0; nt < 8; nt++) {
        int col = nt * 8 + cq * 2;
        g_ctx[row0 + col]     = acc_o[nt][0] * inv0;
        g_ctx[row0 + col + 1] = acc_o[nt][1] * inv0;
        g_ctx[row1 + col]     = acc_o[nt][2] * inv1;
        g_ctx[row1 + col + 1] = acc_o[nt][3] * inv1;
    }
}

// ---------------- residual add + RMSNorm -----------------------------------
__global__ void addnorm_kernel(const float* __restrict__ a, const float* __restrict__ bb,
                               const float* __restrict__ w, float* __restrict__ out) {
    __shared__ float buf[H];
    __shared__ float red[8];
    int t = blockIdx.x, tid = threadIdx.x;
    float ss = 0.f;
    for (int d = tid; d < H; d += 256) {
        float v = a[(size_t)t * H + d] + bb[(size_t)t * H + d];
        buf[d] = v;
        ss += v * v;
    }
    for (int o = 16; o; o >>= 1) ss += __shfl_xor_sync(~0u, ss, o);
    if ((tid & 31) == 0) red[tid >> 5] = ss;
    __syncthreads();
    if (tid < 8) {
        float x = red[tid];
        for (int o = 4; o; o >>= 1) x += __shfl_xor_sync(0xffu, x, o);
        if (tid == 0) red[0] = x;
    }
    __syncthreads();
    float inv = rsqrtf(red[0] / (float)H + 1.1920929e-7f);
    for (int d = tid; d < H; d += 256)
        out[(size_t)t * H + d] = buf[d] * inv * w[d];
}

// ---------------- MoE combine (slots) + residual + RMSNorm -----------------
__global__ void moe_combine_norm(const float* __restrict__ w, float* __restrict__ out) {
    __shared__ float buf[H];
    __shared__ float red[8];
    int t = blockIdx.x, tid = threadIdx.x;
    int s0 = g_slot[t * 2], s1 = g_slot[t * 2 + 1];
    float w0 = g_slotw[t * 2], w1v = g_slotw[t * 2 + 1];
    float ss = 0.f;
    for (int d = tid; d < H; d += 256) {
        float v = g_x1[(size_t)t * H + d]
                + w0 * g_ybuf[(size_t)s0 * H + d]
                + w1v * g_ybuf[(size_t)s1 * H + d];
        buf[d] = v;
        ss += v * v;
    }
    for (int o = 16; o; o >>= 1) ss += __shfl_xor_sync(~0u, ss, o);
    if ((tid & 31) == 0) red[tid >> 5] = ss;
    __syncthreads();
    if (tid < 8) {
        float x = red[tid];
        for (int o = 4; o; o >>= 1) x += __shfl_xor_sync(0xffu, x, o);
        if (tid == 0) red[0] = x;
    }
    __syncthreads();
    float inv = rsqrtf(red[0] / (float)H + 1.1920929e-7f);
    for (int d = tid; d < H; d += 256)
        out[(size_t)t * H + d] = buf[d] * inv * w[d];
}

// ---------------- router -----------------------------------------------------
__global__ void router_kernel(const float* __restrict__ gate_w) {
    int warp = threadIdx.x >> 5, lane = threadIdx.x & 31;
    int t = blockIdx.x * 8 + warp;
    float acc[E];
#pragma unroll
    for (int e = 0; e < E; e++) acc[e] = 0.f;
    const float* xr = g_x1 + (size_t)t * H;
    for (int d = lane; d < H; d += 32) {
        float xv = xr[d];
        const float* g = gate_w + (size_t)d * E;
#pragma unroll
        for (int e = 0; e < E; e++) acc[e] += xv * g[e];
    }
#pragma unroll
    for (int e = 0; e < E; e++)
        for (int o = 16; o; o >>= 1) acc[e] += __shfl_xor_sync(~0u, acc[e], o);
    if (lane == 0) {
        float mx = acc[0];
#pragma unroll
        for (int e = 1; e < E; e++) mx = fmaxf(mx, acc[e]);
        float p[E]; float sum = 0.f;
#pragma unroll
        for (int e = 0; e < E; e++) { p[e] = expf(acc[e] - mx); sum += p[e]; }
        float inv = 1.f / sum;
#pragma unroll
        for (int e = 0; e < E; e++) p[e] *= inv;
        int i1 = 0;
#pragma unroll
        for (int e = 1; e < E; e++) if (p[e] > p[i1]) i1 = e;
        int i2 = -1;
#pragma unroll
        for (int e = 0; e < E; e++) {
            if (e == i1) continue;
            if (i2 < 0 || p[e] > p[i2]) i2 = e;
        }
        float s2 = p[i1] + p[i2];
        float w1n = p[i1] / s2, w2n = p[i2] / s2;
        int pos = atomicAdd(&g_cnt[i1], 1);
        g_tok[i1 * T + pos] = t;
        g_slot[t * 2] = i1 * T + pos;
        g_slotw[t * 2] = w1n;
        pos = atomicAdd(&g_cnt[i2], 1);
        g_tok[i2 * T + pos] = t;
        g_slot[t * 2 + 1] = i2 * T + pos;
        g_slotw[t * 2 + 1] = w2n;
#pragma unroll
        for (int e = 0; e < E; e++) atomicAdd(&g_probsum[e], p[e]);
    }
}

__global__ void aux_kernel(float* out) {
    float a = 0.f;
    for (int e = 0; e < E; e++)
        a += ((float)g_cnt[e] / (float)T) * (g_probsum[e] / (float)T);
    out[0] = (float)E * a;
}

// ---------------------------------------------------------------------------
extern "C" void kernel_launch(void* const* d_in, const int* in_sizes, int n_in,
                              void* d_out, int out_size) {
    const float* x      = (const float*)d_in[0];
    const int*   mask   = (const int*)  d_in[1];
    const float* qkv_w  = (const float*)d_in[2];
    const float* out_w  = (const float*)d_in[3];
    const float* gate_w = (const float*)d_in[4];
    const float* w1     = (const float*)d_in[5];
    const float* w2     = (const float*)d_in[6];
    const float* n1     = (const float*)d_in[7];
    const float* n2     = (const float*)d_in[8];
    float* out = (float*)d_out;

    float *p_qkv, *p_ctx, *p_attn, *p_x1, *p_hmid;
    cudaGetSymbolAddress((void**)&p_qkv,  g_qkv);
    cudaGetSymbolAddress((void**)&p_ctx,  g_ctx);
    cudaGetSymbolAddress((void**)&p_attn, g_attn);
    cudaGetSymbolAddress((void**)&p_x1,   g_x1);
    cudaGetSymbolAddress((void**)&p_hmid, g_hmid);

    static bool attr_set = false;
    if (!attr_set) {
        cudaFuncSetAttribute(flash3_kernel,
                             cudaFuncAttributeMaxDynamicSharedMemorySize, FLASH_SMEM);
        attr_set = true;
    }

    zero_small<<<1, 32>>>();

    gemm_tf32<0><<<dim3(H3 / BN, T / BM, 1), 256>>>(x, qkv_w, p_qkv, T, H3, H);

    rope_kernel<<<(T * NH * 32 + 255) / 256, 256>>>();

    flash3_kernel<<<dim3(S / 64, NH, B), 128, FLASH_SMEM>>>(mask);

    gemm_tf32<0><<<dim3(H / BN, T / BM, 1), 256>>>(p_ctx, out_w, p_attn, T, H, H);

    addnorm_kernel<<<T, 256>>>(x, p_attn, n1, p_x1);

    router_kernel<<<T / 8, 256>>>(gate_w);
    aux_kernel<<<1, 1>>>(out + (size_t)T * H);

    gemm_tf32<1><<<dim3(F / BN, T / BM, E), 256>>>(p_x1, w1, nullptr, T, F, H);
    gemm_tf32<2><<<dim3(H / BN, T / BM, E), 256>>>(p_hmid, w2, nullptr, T, H, F);

    moe_combine_norm<<<T, 256>>>(n2, out);
}

// round 7
// speedup vs baseline: 2.9887x; 1.1802x over previous
#include <cuda_runtime.h>
#include <math.h>

#define B 4
#define S 2048
#define H 768
#define NH 12
#define HD 64
#define E 8
#define TOPK 2
#define F 3072
#define T (B*S)      /* 8192 tokens */
#define H3 (3*H)     /* 2304 */

// ---------------- scratch (device globals: no runtime allocation) ----------
__device__ float g_qkv[(size_t)T*H3];
__device__ float g_ctx[(size_t)T*H];
__device__ float g_attn[(size_t)T*H];
__device__ float g_x1[(size_t)T*H];
__device__ float g_hmid[(size_t)E*T*F];
__device__ float g_ybuf[(size_t)E*T*H];
__device__ int   g_cnt[E];
__device__ float g_probsum[E];
__device__ int   g_tok[E*T];
__device__ int   g_slot[T*TOPK];
__device__ float g_slotw[T*TOPK];

__global__ void zero_small() {
    if (threadIdx.x < E) { g_cnt[threadIdx.x] = 0; g_probsum[threadIdx.x] = 0.f; }
}

__device__ __forceinline__ unsigned f2tf(float x) {
    unsigned u; asm("cvt.rna.tf32.f32 %0, %1;" : "=r"(u) : "f"(x)); return u;
}

#define MMA_TF32(d0,d1,d2,d3,a0,a1,a2,a3,b0,b1) \
    asm volatile("mma.sync.aligned.m16n8k8.row.col.f32.tf32.tf32.f32 " \
                 "{%0,%1,%2,%3},{%4,%5,%6,%7},{%8,%9},{%0,%1,%2,%3};" \
                 : "+f"(d0), "+f"(d1), "+f"(d2), "+f"(d3) \
                 : "r"(a0), "r"(a1), "r"(a2), "r"(a3), "r"(b0), "r"(b1))

__device__ __forceinline__ void cp_async16(void* smem_dst, const void* gsrc) {
    unsigned saddr = (unsigned)__cvta_generic_to_shared(smem_dst);
    asm volatile("cp.async.ca.shared.global [%0], [%1], 16;" :: "r"(saddr), "l"(gsrc));
}
#define CP_COMMIT asm volatile("cp.async.commit_group;")
#define CP_WAIT0  asm volatile("cp.async.wait_group 0;")
#define CP_WAIT1  asm volatile("cp.async.wait_group 1;")

// ---------------- tf32 tensor-core GEMM, 3-stage full-async pipeline -------
#define BM 128
#define BN 128
#define BK 16
#define AS_STRIDE 20
#define BS_STRIDE 132
#define GEMM_SMEM (3 * (BM*AS_STRIDE + BK*BS_STRIDE) * 4)   /* 56064 B */

template<int MODE>
__global__ void __launch_bounds__(256) gemm_tf32(
    const float* __restrict__ A, const float* __restrict__ W,
    float* __restrict__ Cout, int M, int N, int K)
{
    extern __shared__ float gsm[];
    float* AsP = gsm;                              // [3][BM][20]
    float* BsP = gsm + 3 * BM * AS_STRIDE;         // [3][BK][132]
    __shared__ int rt_s[BM];

    int e = blockIdx.z;
    int c = M;
    int r0 = blockIdx.y * BM;
    if (MODE != 0) {
        c = g_cnt[e];
        if (r0 >= c) return;
    }
    int col0 = blockIdx.x * BN;
    int tid = threadIdx.x;

    const float* Ab = A;
    const float* Wb = W;
    if (MODE == 1) { Wb = W + (size_t)e * K * N; }
    if (MODE == 2) { Ab = A + (size_t)e * T * K; Wb = W + (size_t)e * K * N; }

    if (MODE == 1) {
        if (tid < BM) {
            int r = r0 + tid;
            int tt = (r < c) ? g_tok[e * T + r] : 0;
            rt_s[tid] = tt;
        }
        __syncthreads();
    }

    int lane = tid & 31, warp = tid >> 5;
    int wm = warp >> 2, wn = warp & 3;
    int g = lane >> 2, cq = lane & 3;

    auto issueA = [&](int stage, int k0) {
        float* dst = AsP + stage * BM * AS_STRIDE;
#pragma unroll
        for (int i = 0; i < 2; i++) {
            int lin = tid + i * 256;
            int r = lin >> 2, kq = (lin & 3) * 4;
            const float* src;
            if (MODE == 0)      src = Ab + (size_t)(r0 + r) * K + k0 + kq;
            else if (MODE == 1) src = Ab + (size_t)rt_s[r] * K + k0 + kq;
            else                src = Ab + (size_t)(r0 + r) * K + k0 + kq;
            cp_async16(dst + r * AS_STRIDE + kq, src);
        }
    };
    auto issueB = [&](int stage, int k0) {
        float* dst = BsP + stage * BK * BS_STRIDE;
#pragma unroll
        for (int i = 0; i < 2; i++) {
            int lin = tid + i * 256;
            int r = lin >> 5, nq = (lin & 31) * 4;
            cp_async16(dst + r * BS_STRIDE + nq, Wb + (size_t)(k0 + r) * N + col0 + nq);
        }
    };

    float acc[4][4][4];
#pragma unroll
    for (int i = 0; i < 4; i++)
#pragma unroll
        for (int j = 0; j < 4; j++)
#pragma unroll
            for (int k = 0; k < 4; k++) acc[i][j][k] = 0.f;

    int nIter = K / BK;
    issueA(0, 0); issueB(0, 0); CP_COMMIT;
    issueA(1, BK); issueB(1, BK); CP_COMMIT;
    int cur = 0;

    for (int it = 0; it < nIter; it++) {
        if (it < nIter - 1) { CP_WAIT1; } else { CP_WAIT0; }
        __syncthreads();
        if (it + 2 < nIter) {
            int st = (it + 2) % 3;
            issueA(st, (it + 2) * BK);
            issueB(st, (it + 2) * BK);
            CP_COMMIT;
        }
        const float* Ac = AsP + cur * BM * AS_STRIDE;
        const float* Bc = BsP + cur * BK * BS_STRIDE;
#pragma unroll
        for (int kk = 0; kk < BK; kk += 8) {
            unsigned a[4][4], b[4][2];
#pragma unroll
            for (int mt = 0; mt < 4; mt++) {
                int m0 = wm * 64 + mt * 16;
                a[mt][0] = f2tf(Ac[(m0 + g    ) * AS_STRIDE + kk + cq    ]);
                a[mt][1] = f2tf(Ac[(m0 + g + 8) * AS_STRIDE + kk + cq    ]);
                a[mt][2] = f2tf(Ac[(m0 + g    ) * AS_STRIDE + kk + cq + 4]);
                a[mt][3] = f2tf(Ac[(m0 + g + 8) * AS_STRIDE + kk + cq + 4]);
            }
#pragma unroll
            for (int nt = 0; nt < 4; nt++) {
                int n0 = wn * 32 + nt * 8;
                b[nt][0] = f2tf(Bc[(kk + cq    ) * BS_STRIDE + n0 + g]);
                b[nt][1] = f2tf(Bc[(kk + cq + 4) * BS_STRIDE + n0 + g]);
            }
#pragma unroll
            for (int mt = 0; mt < 4; mt++)
#pragma unroll
                for (int nt = 0; nt < 4; nt++) {
                    MMA_TF32(acc[mt][nt][0], acc[mt][nt][1], acc[mt][nt][2], acc[mt][nt][3],
                             a[mt][0], a[mt][1], a[mt][2], a[mt][3],
                             b[nt][0], b[nt][1]);
                }
        }
        cur = (cur + 1) % 3;
    }

#pragma unroll
    for (int mt = 0; mt < 4; mt++) {
#pragma unroll
        for (int nt = 0; nt < 4; nt++) {
#pragma unroll
            for (int half = 0; half < 2; half++) {
                int lrow = wm * 64 + mt * 16 + g + half * 8;
                int col = col0 + wn * 32 + nt * 8 + cq * 2;
                float v0 = acc[mt][nt][half * 2 + 0];
                float v1 = acc[mt][nt][half * 2 + 1];
                if (MODE == 0) {
                    Cout[(size_t)(r0 + lrow) * N + col]     = v0;
                    Cout[(size_t)(r0 + lrow) * N + col + 1] = v1;
                } else if (MODE == 1) {
                    int r = r0 + lrow;
                    if (r < c) {
                        float g0 = 0.5f * v0 * (1.f + erff(v0 * 0.70710678118f));
                        float g1 = 0.5f * v1 * (1.f + erff(v1 * 0.70710678118f));
                        g_hmid[((size_t)e * T + r) * F + col]     = g0;
                        g_hmid[((size_t)e * T + r) * F + col + 1] = g1;
                    }
                } else {
                    int r = r0 + lrow;
                    if (r < c) {
                        g_ybuf[((size_t)e * T + r) * H + col]     = v0;
                        g_ybuf[((size_t)e * T + r) * H + col + 1] = v1;
                    }
                }
            }
        }
    }
}

// ---------------- RoPE applied in-place to q,k inside g_qkv ----------------
__global__ void rope_kernel() {
    int idx = blockIdx.x * blockDim.x + threadIdx.x;
    if (idx >= T * NH * 32) return;
    int i = idx & 31;
    int h = (idx >> 5) % NH;
    int t = idx / (32 * NH);
    int s = t % S;
    float invf = expf(-(float)i * (9.210340371976184f / 32.f));
    float th = (float)s * invf;
    float c = cosf(th), sn = sinf(th);
    float* p = g_qkv + (size_t)t * H3 + h * 192;
    float q1 = p[i], q2 = p[i + 32];
    p[i]      = q1 * c - q2 * sn;
    p[i + 32] = q2 * c + q1 * sn;
    float k1 = p[64 + i], k2 = p[64 + i + 32];
    p[64 + i]      = k1 * c - k2 * sn;
    p[64 + i + 32] = k2 * c + k1 * sn;
}

// ---------------- flash attention v4: 128 q/block, Q in regs, cp.async -----
// grid (S/128, NH, B), 128 threads (4 warps); each warp owns two 16-row tiles.
#define KS_STRIDE 68
#define VS_STRIDE 72
#define FLASH_SMEM ((2*64*KS_STRIDE + 2*64*VS_STRIDE) * 4 + 2 * 64 * 4)

__global__ void __launch_bounds__(128) flash4_kernel(const int* __restrict__ mask) {
    extern __shared__ float fsm[];
    float* KsB = fsm;                          // [2][64][68]
    float* VsB = KsB + 2 * 64 * KS_STRIDE;     // [2][64][72]
    int*   MkB = (int*)(VsB + 2 * 64 * VS_STRIDE); // [2][64]

    int tid = threadIdx.x;
    int lane = tid & 31, warp = tid >> 5;
    int g = lane >> 2, cq = lane & 3;
    int q0 = blockIdx.x * 128, h = blockIdx.y, b = blockIdx.z;
    const float* base = g_qkv + (size_t)b * S * H3 + (size_t)h * 192;
    int m0 = warp * 16;

    // ---- Q fragments in registers (scaled, tf32-rounded once) ----
    unsigned qf[2][8][4];
#pragma unroll
    for (int mb = 0; mb < 2; mb++) {
        const float* qr0 = base + (size_t)(q0 + mb * 64 + m0 + g) * H3;
        const float* qr1 = qr0 + (size_t)8 * H3;
#pragma unroll
        for (int cc = 0; cc < 8; cc++) {
            qf[mb][cc][0] = f2tf(qr0[cc * 8 + cq]     * 0.125f);
            qf[mb][cc][1] = f2tf(qr1[cc * 8 + cq]     * 0.125f);
            qf[mb][cc][2] = f2tf(qr0[cc * 8 + cq + 4] * 0.125f);
            qf[mb][cc][3] = f2tf(qr1[cc * 8 + cq + 4] * 0.125f);
        }
    }

    // cp.async issue for one K/V/mask tile
    int lr = tid >> 1, lc = (tid & 1) * 32;
    auto issueKV = [&](int buf, int k0) {
        const float* kp = base + (size_t)(k0 + lr) * H3;
        float* kd = KsB + buf * 64 * KS_STRIDE + lr * KS_STRIDE + lc;
        float* vd = VsB + buf * 64 * VS_STRIDE + lr * VS_STRIDE + lc;
#pragma unroll
        for (int j = 0; j < 8; j++) {
            cp_async16(kd + j * 4, kp + 64  + lc + j * 4);
            cp_async16(vd + j * 4, kp + 128 + lc + j * 4);
        }
        if (tid < 16)
            cp_async16(MkB + buf * 64 + tid * 4, mask + b * S + k0 + tid * 4);
    };

    float acc_o[2][8][4];
#pragma unroll
    for (int mb = 0; mb < 2; mb++)
#pragma unroll
        for (int nt = 0; nt < 8; nt++)
#pragma unroll
            for (int j = 0; j < 4; j++) acc_o[mb][nt][j] = 0.f;
    float mr[2][2] = {{-1e30f, -1e30f}, {-1e30f, -1e30f}};
    float lr_[2][2] = {{0.f, 0.f}, {0.f, 0.f}};

    unsigned fullm = 0xffffffffu;
    int qbase = lane & ~3;
    int s_lo = qbase + (cq >> 1);
    int s_hi = qbase + 2 + (cq >> 1);
    bool odd = (cq & 1);

    issueKV(0, 0);
    CP_COMMIT;
    int cur = 0;

    for (int k0 = 0; k0 < S; k0 += 64) {
        CP_WAIT0;
        __syncthreads();
        if (k0 + 64 < S) {
            issueKV(cur ^ 1, k0 + 64);
            CP_COMMIT;
        }
        const float* Kc = KsB + cur * 64 * KS_STRIDE;
        const float* Vc = VsB + cur * 64 * VS_STRIDE;
        const int*   Mc = MkB + cur * 64;

#pragma unroll
        for (int mb = 0; mb < 2; mb++) {
            // ---- S = Q K^T (16x64) ----
            float sacc[8][4];
#pragma unroll
            for (int nt = 0; nt < 8; nt++)
#pragma unroll
                for (int j = 0; j < 4; j++) sacc[nt][j] = 0.f;
#pragma unroll
            for (int kk = 0; kk < 64; kk += 8) {
                int cc = kk >> 3;
#pragma unroll
                for (int nt = 0; nt < 8; nt++) {
                    unsigned b0 = f2tf(Kc[(nt * 8 + g) * KS_STRIDE + kk + cq    ]);
                    unsigned b1 = f2tf(Kc[(nt * 8 + g) * KS_STRIDE + kk + cq + 4]);
                    MMA_TF32(sacc[nt][0], sacc[nt][1], sacc[nt][2], sacc[nt][3],
                             qf[mb][cc][0], qf[mb][cc][1], qf[mb][cc][2], qf[mb][cc][3],
                             b0, b1);
                }
            }

            // ---- mask + online softmax ----
            float mx0 = -1e30f, mx1 = -1e30f;
#pragma unroll
            for (int nt = 0; nt < 8; nt++) {
                float mk0 = (Mc[nt * 8 + cq * 2]     == 0) ? -1e30f : 0.f;
                float mk1 = (Mc[nt * 8 + cq * 2 + 1] == 0) ? -1e30f : 0.f;
                sacc[nt][0] += mk0; sacc[nt][1] += mk1;
                sacc[nt][2] += mk0; sacc[nt][3] += mk1;
                mx0 = fmaxf(mx0, fmaxf(sacc[nt][0], sacc[nt][1]));
                mx1 = fmaxf(mx1, fmaxf(sacc[nt][2], sacc[nt][3]));
            }
            mx0 = fmaxf(mx0, __shfl_xor_sync(fullm, mx0, 1));
            mx0 = fmaxf(mx0, __shfl_xor_sync(fullm, mx0, 2));
            mx1 = fmaxf(mx1, __shfl_xor_sync(fullm, mx1, 1));
            mx1 = fmaxf(mx1, __shfl_xor_sync(fullm, mx1, 2));
            float newm0 = fmaxf(mr[mb][0], mx0), newm1 = fmaxf(mr[mb][1], mx1);
            float sc0 = __expf(mr[mb][0] - newm0), sc1 = __expf(mr[mb][1] - newm1);
            mr[mb][0] = newm0; mr[mb][1] = newm1;
            float ps0 = 0.f, ps1 = 0.f;
#pragma unroll
            for (int nt = 0; nt < 8; nt++) {
                sacc[nt][0] = __expf(sacc[nt][0] - newm0);
                sacc[nt][1] = __expf(sacc[nt][1] - newm0);
                sacc[nt][2] = __expf(sacc[nt][2] - newm1);
                sacc[nt][3] = __expf(sacc[nt][3] - newm1);
                ps0 += sacc[nt][0] + sacc[nt][1];
                ps1 += sacc[nt][2] + sacc[nt][3];
                acc_o[mb][nt][0] *= sc0; acc_o[mb][nt][1] *= sc0;
                acc_o[mb][nt][2] *= sc1; acc_o[mb][nt][3] *= sc1;
            }
            ps0 += __shfl_xor_sync(fullm, ps0, 1); ps0 += __shfl_xor_sync(fullm, ps0, 2);
            ps1 += __shfl_xor_sync(fullm, ps1, 1); ps1 += __shfl_xor_sync(fullm, ps1, 2);
            lr_[mb][0] = lr_[mb][0] * sc0 + ps0;
            lr_[mb][1] = lr_[mb][1] * sc1 + ps1;

            // ---- O += P V ----
#pragma unroll
            for (int kt = 0; kt < 8; kt++) {
                unsigned p0 = f2tf(sacc[kt][0]), p1 = f2tf(sacc[kt][1]);
                unsigned p2 = f2tf(sacc[kt][2]), p3 = f2tf(sacc[kt][3]);
                unsigned u0 = __shfl_sync(fullm, p0, s_lo), u1 = __shfl_sync(fullm, p1, s_lo);
                unsigned a0 = odd ? u1 : u0;
                unsigned w0 = __shfl_sync(fullm, p2, s_lo), w1 = __shfl_sync(fullm, p3, s_lo);
                unsigned a1 = odd ? w1 : w0;
                unsigned v0 = __shfl_sync(fullm, p0, s_hi), v1 = __shfl_sync(fullm, p1, s_hi);
                unsigned a2 = odd ? v1 : v0;
                unsigned x0 = __shfl_sync(fullm, p2, s_hi), x1 = __shfl_sync(fullm, p3, s_hi);
                unsigned a3 = odd ? x1 : x0;
#pragma unroll
                for (int nt = 0; nt < 8; nt++) {
                    unsigned b0 = f2tf(Vc[(kt * 8 + cq    ) * VS_STRIDE + nt * 8 + g]);
                    unsigned b1 = f2tf(Vc[(kt * 8 + cq + 4) * VS_STRIDE + nt * 8 + g]);
                    MMA_TF32(acc_o[mb][nt][0], acc_o[mb][nt][1],
                             acc_o[mb][nt][2], acc_o[mb][nt][3],
                             a0, a1, a2, a3, b0, b1);
                }
            }
        }
        cur ^= 1;
    }

    // ---- epilogue ----
#pragma unroll
    for (int mb = 0; mb < 2; mb++) {
        float inv0 = 1.f / lr_[mb][0], inv1 = 1.f / lr_[mb][1];
        size_t row0 = (size_t)(b * S + q0 + mb * 64 + m0 + g) * H + h * HD;
        size_t row1 = row0 + (size_t)8 * H;
#pragma unroll
        for (int nt = 0; nt < 8; nt++) {
            int col = nt * 8 + cq * 2;
            g_ctx[row0 + col]     = acc_o[mb][nt][0] * inv0;
            g_ctx[row0 + col + 1] = acc_o[mb][nt][1] * inv0;
            g_ctx[row1 + col]     = acc_o[mb][nt][2] * inv1;
            g_ctx[row1 + col + 1] = acc_o[mb][nt][3] * inv1;
        }
    }
}

// ---------------- residual add + RMSNorm -----------------------------------
__global__ void addnorm_kernel(const float* __restrict__ a, const float* __restrict__ bb,
                               const float* __restrict__ w, float* __restrict__ out) {
    __shared__ float buf[H];
    __shared__ float red[8];
    int t = blockIdx.x, tid = threadIdx.x;
    float ss = 0.f;
    for (int d = tid; d < H; d += 256) {
        float v = a[(size_t)t * H + d] + bb[(size_t)t * H + d];
        buf[d] = v;
        ss += v * v;
    }
    for (int o = 16; o; o >>= 1) ss += __shfl_xor_sync(~0u, ss, o);
    if ((tid & 31) == 0) red[tid >> 5] = ss;
    __syncthreads();
    if (tid < 8) {
        float x = red[tid];
        for (int o = 4; o; o >>= 1) x += __shfl_xor_sync(0xffu, x, o);
        if (tid == 0) red[0] = x;
    }
    __syncthreads();
    float inv = rsqrtf(red[0] / (float)H + 1.1920929e-7f);
    for (int d = tid; d < H; d += 256)
        out[(size_t)t * H + d] = buf[d] * inv * w[d];
}

// ---------------- MoE combine (slots) + residual + RMSNorm -----------------
__global__ void moe_combine_norm(const float* __restrict__ w, float* __restrict__ out) {
    __shared__ float buf[H];
    __shared__ float red[8];
    int t = blockIdx.x, tid = threadIdx.x;
    int s0 = g_slot[t * 2], s1 = g_slot[t * 2 + 1];
    float w0 = g_slotw[t * 2], w1v = g_slotw[t * 2 + 1];
    float ss = 0.f;
    for (int d = tid; d < H; d += 256) {
        float v = g_x1[(size_t)t * H + d]
                + w0 * g_ybuf[(size_t)s0 * H + d]
                + w1v * g_ybuf[(size_t)s1 * H + d];
        buf[d] = v;
        ss += v * v;
    }
    for (int o = 16; o; o >>= 1) ss += __shfl_xor_sync(~0u, ss, o);
    if ((tid & 31) == 0) red[tid >> 5] = ss;
    __syncthreads();
    if (tid < 8) {
        float x = red[tid];
        for (int o = 4; o; o >>= 1) x += __shfl_xor_sync(0xffu, x, o);
        if (tid == 0) red[0] = x;
    }
    __syncthreads();
    float inv = rsqrtf(red[0] / (float)H + 1.1920929e-7f);
    for (int d = tid; d < H; d += 256)
        out[(size_t)t * H + d] = buf[d] * inv * w[d];
}

// ---------------- router -----------------------------------------------------
__global__ void router_kernel(const float* __restrict__ gate_w) {
    int warp = threadIdx.x >> 5, lane = threadIdx.x & 31;
    int t = blockIdx.x * 8 + warp;
    float acc[E];
#pragma unroll
    for (int e = 0; e < E; e++) acc[e] = 0.f;
    const float* xr = g_x1 + (size_t)t * H;
    for (int d = lane; d < H; d += 32) {
        float xv = xr[d];
        const float* g = gate_w + (size_t)d * E;
#pragma unroll
        for (int e = 0; e < E; e++) acc[e] += xv * g[e];
    }
#pragma unroll
    for (int e = 0; e < E; e++)
        for (int o = 16; o; o >>= 1) acc[e] += __shfl_xor_sync(~0u, acc[e], o);
    if (lane == 0) {
        float mx = acc[0];
#pragma unroll
        for (int e = 1; e < E; e++) mx = fmaxf(mx, acc[e]);
        float p[E]; float sum = 0.f;
#pragma unroll
        for (int e = 0; e < E; e++) { p[e] = expf(acc[e] - mx); sum += p[e]; }
        float inv = 1.f / sum;
#pragma unroll
        for (int e = 0; e < E; e++) p[e] *= inv;
        int i1 = 0;
#pragma unroll
        for (int e = 1; e < E; e++) if (p[e] > p[i1]) i1 = e;
        int i2 = -1;
#pragma unroll
        for (int e = 0; e < E; e++) {
            if (e == i1) continue;
            if (i2 < 0 || p[e] > p[i2]) i2 = e;
        }
        float s2 = p[i1] + p[i2];
        float w1n = p[i1] / s2, w2n = p[i2] / s2;
        int pos = atomicAdd(&g_cnt[i1], 1);
        g_tok[i1 * T + pos] = t;
        g_slot[t * 2] = i1 * T + pos;
        g_slotw[t * 2] = w1n;
        pos = atomicAdd(&g_cnt[i2], 1);
        g_tok[i2 * T + pos] = t;
        g_slot[t * 2 + 1] = i2 * T + pos;
        g_slotw[t * 2 + 1] = w2n;
#pragma unroll
        for (int e = 0; e < E; e++) atomicAdd(&g_probsum[e], p[e]);
    }
}

__global__ void aux_kernel(float* out) {
    float a = 0.f;
    for (int e = 0; e < E; e++)
        a += ((float)g_cnt[e] / (float)T) * (g_probsum[e] / (float)T);
    out[0] = (float)E * a;
}

// ---------------------------------------------------------------------------
extern "C" void kernel_launch(void* const* d_in, const int* in_sizes, int n_in,
                              void* d_out, int out_size) {
    const float* x      = (const float*)d_in[0];
    const int*   mask   = (const int*)  d_in[1];
    const float* qkv_w  = (const float*)d_in[2];
    const float* out_w  = (const float*)d_in[3];
    const float* gate_w = (const float*)d_in[4];
    const float* w1     = (const float*)d_in[5];
    const float* w2     = (const float*)d_in[6];
    const float* n1     = (const float*)d_in[7];
    const float* n2     = (const float*)d_in[8];
    float* out = (float*)d_out;

    float *p_qkv, *p_ctx, *p_attn, *p_x1, *p_hmid;
    cudaGetSymbolAddress((void**)&p_qkv,  g_qkv);
    cudaGetSymbolAddress((void**)&p_ctx,  g_ctx);
    cudaGetSymbolAddress((void**)&p_attn, g_attn);
    cudaGetSymbolAddress((void**)&p_x1,   g_x1);
    cudaGetSymbolAddress((void**)&p_hmid, g_hmid);

    static bool attr_set = false;
    if (!attr_set) {
        cudaFuncSetAttribute(flash4_kernel,
                             cudaFuncAttributeMaxDynamicSharedMemorySize, FLASH_SMEM);
        cudaFuncSetAttribute(gemm_tf32<0>,
                             cudaFuncAttributeMaxDynamicSharedMemorySize, GEMM_SMEM);
        cudaFuncSetAttribute(gemm_tf32<1>,
                             cudaFuncAttributeMaxDynamicSharedMemorySize, GEMM_SMEM);
        cudaFuncSetAttribute(gemm_tf32<2>,
                             cudaFuncAttributeMaxDynamicSharedMemorySize, GEMM_SMEM);
        attr_set = true;
    }

    zero_small<<<1, 32>>>();

    gemm_tf32<0><<<dim3(H3 / BN, T / BM, 1), 256, GEMM_SMEM>>>(x, qkv_w, p_qkv, T, H3, H);

    rope_kernel<<<(T * NH * 32 + 255) / 256, 256>>>();

    flash4_kernel<<<dim3(S / 128, NH, B), 128, FLASH_SMEM>>>(mask);

    gemm_tf32<0><<<dim3(H / BN, T / BM, 1), 256, GEMM_SMEM>>>(p_ctx, out_w, p_attn, T, H, H);

    addnorm_kernel<<<T, 256>>>(x, p_attn, n1, p_x1);

    router_kernel<<<T / 8, 256>>>(gate_w);
    aux_kernel<<<1, 1>>>(out + (size_t)T * H);

    gemm_tf32<1><<<dim3(F / BN, T / BM, E), 256, GEMM_SMEM>>>(p_x1, w1, nullptr, T, F, H);
    gemm_tf32<2><<<dim3(H / BN, T / BM, E), 256, GEMM_SMEM>>>(p_hmid, w2, nullptr, T, H, F);

    moe_combine_norm<<<T, 256>>>(n2, out);
}

// round 8
// speedup vs baseline: 3.2745x; 1.0956x over previous
#include <cuda_runtime.h>
#include <math.h>

#define B 4
#define S 2048
#define H 768
#define NH 12
#define HD 64
#define E 8
#define TOPK 2
#define F 3072
#define T (B*S)      /* 8192 tokens */
#define H3 (3*H)     /* 2304 */

// ---------------- scratch (device globals: no runtime allocation) ----------
__device__ float g_qkv[(size_t)T*H3];
__device__ float g_qT[(size_t)T*H];      // [B][NH][S][HD] tf32-rounded, pre-scaled
__device__ float g_kT[(size_t)T*H];      // [B][NH][S][HD] tf32-rounded
__device__ float g_vT[(size_t)T*H];      // [B][NH][S][HD] tf32-rounded
__device__ float g_xt[(size_t)T*H];      // tf32-rounded x
__device__ float g_ctx[(size_t)T*H];     // tf32-rounded (flash epilogue)
__device__ float g_attn[(size_t)T*H];
__device__ float g_x1[(size_t)T*H];      // exact fp32 (router/combine)
__device__ float g_x1t[(size_t)T*H];     // tf32-rounded x1 (GEMM1 A)
__device__ float g_hmid[(size_t)E*T*F];  // tf32-rounded GELU output
__device__ float g_ybuf[(size_t)E*T*H];
__device__ int   g_cnt[E];
__device__ float g_probsum[E];
__device__ int   g_tok[E*T];
__device__ int   g_slot[T*TOPK];
__device__ float g_slotw[T*TOPK];

__global__ void zero_small() {
    if (threadIdx.x < E) { g_cnt[threadIdx.x] = 0; g_probsum[threadIdx.x] = 0.f; }
}

__device__ __forceinline__ unsigned f2tf(float x) {
    unsigned u; asm("cvt.rna.tf32.f32 %0, %1;" : "=r"(u) : "f"(x)); return u;
}
__device__ __forceinline__ float tfround(float x) {
    return __uint_as_float(f2tf(x));
}

#define MMA_TF32(d0,d1,d2,d3,a0,a1,a2,a3,b0,b1) \
    asm volatile("mma.sync.aligned.m16n8k8.row.col.f32.tf32.tf32.f32 " \
                 "{%0,%1,%2,%3},{%4,%5,%6,%7},{%8,%9},{%0,%1,%2,%3};" \
                 : "+f"(d0), "+f"(d1), "+f"(d2), "+f"(d3) \
                 : "r"(a0), "r"(a1), "r"(a2), "r"(a3), "r"(b0), "r"(b1))

__device__ __forceinline__ void cp_async16(void* smem_dst, const void* gsrc) {
    unsigned saddr = (unsigned)__cvta_generic_to_shared(smem_dst);
    asm volatile("cp.async.ca.shared.global [%0], [%1], 16;" :: "r"(saddr), "l"(gsrc));
}
#define CP_COMMIT asm volatile("cp.async.commit_group;")
#define CP_WAIT0  asm volatile("cp.async.wait_group 0;")
#define CP_WAIT1  asm volatile("cp.async.wait_group 1;")

// ---------------- round-copy: x -> tf32-rounded copy ------------------------
__global__ void round_copy(const float* __restrict__ src, float* __restrict__ dst, int n) {
    int i = blockIdx.x * blockDim.x + threadIdx.x;
    if (i < n) dst[i] = tfround(src[i]);
}

// ---------------- tf32 tensor-core GEMM, 3-stage full-async pipeline -------
// A operands are PRE-ROUNDED to tf32; fragments load raw bits. B cvt'd in loop.
#define BM 128
#define BN 128
#define BK 16
#define AS_STRIDE 20
#define BS_STRIDE 132
#define GEMM_SMEM (3 * (BM*AS_STRIDE + BK*BS_STRIDE) * 4)   /* 56064 B */

template<int MODE>
__global__ void __launch_bounds__(256) gemm_tf32(
    const float* __restrict__ A, const float* __restrict__ W,
    float* __restrict__ Cout, int M, int N, int K)
{
    extern __shared__ float gsm[];
    float* AsP = gsm;                              // [3][BM][20]
    float* BsP = gsm + 3 * BM * AS_STRIDE;         // [3][BK][132]
    __shared__ int rt_s[BM];

    int e = blockIdx.z;
    int c = M;
    int r0 = blockIdx.y * BM;
    if (MODE != 0) {
        c = g_cnt[e];
        if (r0 >= c) return;
    }
    int col0 = blockIdx.x * BN;
    int tid = threadIdx.x;

    const float* Ab = A;
    const float* Wb = W;
    if (MODE == 1) { Wb = W + (size_t)e * K * N; }
    if (MODE == 2) { Ab = A + (size_t)e * T * K; Wb = W + (size_t)e * K * N; }

    if (MODE == 1) {
        if (tid < BM) {
            int r = r0 + tid;
            rt_s[tid] = (r < c) ? g_tok[e * T + r] : 0;
        }
        __syncthreads();
    }

    int lane = tid & 31, warp = tid >> 5;
    int wm = warp >> 2, wn = warp & 3;
    int g = lane >> 2, cq = lane & 3;

    auto issueA = [&](int stage, int k0) {
        float* dst = AsP + stage * BM * AS_STRIDE;
#pragma unroll
        for (int i = 0; i < 2; i++) {
            int lin = tid + i * 256;
            int r = lin >> 2, kq = (lin & 3) * 4;
            const float* src;
            if (MODE == 1) src = Ab + (size_t)rt_s[r] * K + k0 + kq;
            else           src = Ab + (size_t)(r0 + r) * K + k0 + kq;
            cp_async16(dst + r * AS_STRIDE + kq, src);
        }
    };
    auto issueB = [&](int stage, int k0) {
        float* dst = BsP + stage * BK * BS_STRIDE;
#pragma unroll
        for (int i = 0; i < 2; i++) {
            int lin = tid + i * 256;
            int r = lin >> 5, nq = (lin & 31) * 4;
            cp_async16(dst + r * BS_STRIDE + nq, Wb + (size_t)(k0 + r) * N + col0 + nq);
        }
    };

    float acc[4][4][4];
#pragma unroll
    for (int i = 0; i < 4; i++)
#pragma unroll
        for (int j = 0; j < 4; j++)
#pragma unroll
            for (int k = 0; k < 4; k++) acc[i][j][k] = 0.f;

    int nIter = K / BK;
    issueA(0, 0); issueB(0, 0); CP_COMMIT;
    issueA(1, BK); issueB(1, BK); CP_COMMIT;
    int cur = 0;

    for (int it = 0; it < nIter; it++) {
        if (it < nIter - 1) { CP_WAIT1; } else { CP_WAIT0; }
        __syncthreads();
        if (it + 2 < nIter) {
            int st = (it + 2) % 3;
            issueA(st, (it + 2) * BK);
            issueB(st, (it + 2) * BK);
            CP_COMMIT;
        }
        const float* Ac = AsP + cur * BM * AS_STRIDE;
        const float* Bc = BsP + cur * BK * BS_STRIDE;
#pragma unroll
        for (int kk = 0; kk < BK; kk += 8) {
            unsigned a[4][4], b[4][2];
#pragma unroll
            for (int mt = 0; mt < 4; mt++) {
                int m0 = wm * 64 + mt * 16;
                a[mt][0] = __float_as_uint(Ac[(m0 + g    ) * AS_STRIDE + kk + cq    ]);
                a[mt][1] = __float_as_uint(Ac[(m0 + g + 8) * AS_STRIDE + kk + cq    ]);
                a[mt][2] = __float_as_uint(Ac[(m0 + g    ) * AS_STRIDE + kk + cq + 4]);
                a[mt][3] = __float_as_uint(Ac[(m0 + g + 8) * AS_STRIDE + kk + cq + 4]);
            }
#pragma unroll
            for (int nt = 0; nt < 4; nt++) {
                int n0 = wn * 32 + nt * 8;
                b[nt][0] = f2tf(Bc[(kk + cq    ) * BS_STRIDE + n0 + g]);
                b[nt][1] = f2tf(Bc[(kk + cq + 4) * BS_STRIDE + n0 + g]);
            }
#pragma unroll
            for (int mt = 0; mt < 4; mt++)
#pragma unroll
                for (int nt = 0; nt < 4; nt++) {
                    MMA_TF32(acc[mt][nt][0], acc[mt][nt][1], acc[mt][nt][2], acc[mt][nt][3],
                             a[mt][0], a[mt][1], a[mt][2], a[mt][3],
                             b[nt][0], b[nt][1]);
                }
        }
        cur = (cur + 1) % 3;
    }

#pragma unroll
    for (int mt = 0; mt < 4; mt++) {
#pragma unroll
        for (int nt = 0; nt < 4; nt++) {
#pragma unroll
            for (int half = 0; half < 2; half++) {
                int lrow = wm * 64 + mt * 16 + g + half * 8;
                int col = col0 + wn * 32 + nt * 8 + cq * 2;
                float v0 = acc[mt][nt][half * 2 + 0];
                float v1 = acc[mt][nt][half * 2 + 1];
                if (MODE == 0) {
                    Cout[(size_t)(r0 + lrow) * N + col]     = v0;
                    Cout[(size_t)(r0 + lrow) * N + col + 1] = v1;
                } else if (MODE == 1) {
                    int r = r0 + lrow;
                    if (r < c) {
                        float g0 = 0.5f * v0 * (1.f + erff(v0 * 0.70710678118f));
                        float g1 = 0.5f * v1 * (1.f + erff(v1 * 0.70710678118f));
                        // pre-round for GEMM2 consumption
                        g_hmid[((size_t)e * T + r) * F + col]     = tfround(g0);
                        g_hmid[((size_t)e * T + r) * F + col + 1] = tfround(g1);
                    }
                } else {
                    int r = r0 + lrow;
                    if (r < c) {
                        g_ybuf[((size_t)e * T + r) * H + col]     = v0;
                        g_ybuf[((size_t)e * T + r) * H + col + 1] = v1;
                    }
                }
            }
        }
    }
}

// ---------------- RoPE + repack into contiguous tf32 Q/K/V -----------------
__global__ void rope2_kernel() {
    int idx = blockIdx.x * blockDim.x + threadIdx.x;
    if (idx >= T * NH * 32) return;
    int i = idx & 31;
    int h = (idx >> 5) % NH;
    int t = idx / (32 * NH);
    int b = t / S, s = t % S;
    float invf = expf(-(float)i * (9.210340371976184f / 32.f));
    float th = (float)s * invf;
    float c = cosf(th), sn = sinf(th);
    const float* p = g_qkv + (size_t)t * H3 + h * 192;
    size_t dbase = ((size_t)(b * NH + h) * S + s) * HD;
    float q1 = p[i], q2 = p[i + 32];
    g_qT[dbase + i]      = tfround((q1 * c - q2 * sn) * 0.125f);
    g_qT[dbase + i + 32] = tfround((q2 * c + q1 * sn) * 0.125f);
    float k1 = p[64 + i], k2 = p[64 + i + 32];
    g_kT[dbase + i]      = tfround(k1 * c - k2 * sn);
    g_kT[dbase + i + 32] = tfround(k2 * c + k1 * sn);
    g_vT[dbase + i]      = tfround(p[128 + i]);
    g_vT[dbase + i + 32] = tfround(p[128 + i + 32]);
}

// ---------------- flash attention v5: 8 warps, P via smem, raw tf32 --------
// grid (S/128, NH, B), 256 threads; warp w owns query rows q0+16w..+15.
#define KS 68
#define VS 72
#define PS 68
#define FLASH_SMEM ((2*64*KS + 2*64*VS + 8*16*PS) * 4 + 2 * 64 * 4)

__global__ void __launch_bounds__(256) flash5_kernel(const int* __restrict__ mask) {
    extern __shared__ unsigned usm[];
    unsigned* Kb = usm;                         // [2][64][KS]
    unsigned* Vb = Kb + 2 * 64 * KS;            // [2][64][VS]
    unsigned* Pb = Vb + 2 * 64 * VS;            // [8][16][PS]
    int*      Mb = (int*)(Pb + 8 * 16 * PS);    // [2][64]

    int tid = threadIdx.x;
    int lane = tid & 31, warp = tid >> 5;
    int g = lane >> 2, cq = lane & 3;
    int q0 = blockIdx.x * 128, h = blockIdx.y, b = blockIdx.z;
    size_t bh = (size_t)(b * NH + h) * S;

    // ---- Q fragments in registers (raw, pre-rounded+scaled) ----
    unsigned qf[8][4];
    {
        const float* qr0 = g_qT + (bh + q0 + warp * 16 + g) * HD;
        const float* qr1 = qr0 + 8 * HD;
#pragma unroll
        for (int cc = 0; cc < 8; cc++) {
            qf[cc][0] = __float_as_uint(qr0[cc * 8 + cq]);
            qf[cc][1] = __float_as_uint(qr1[cc * 8 + cq]);
            qf[cc][2] = __float_as_uint(qr0[cc * 8 + cq + 4]);
            qf[cc][3] = __float_as_uint(qr1[cc * 8 + cq + 4]);
        }
    }

    // cp.async: 256 threads, 64 rows, 4 threads/row x 64B
    int lrow = tid >> 2, lc = (tid & 3) * 16;
    auto issueKV = [&](int buf, int k0) {
        const float* kp = g_kT + (bh + k0 + lrow) * HD + lc;
        const float* vp = g_vT + (bh + k0 + lrow) * HD + lc;
        unsigned* kd = Kb + buf * 64 * KS + lrow * KS + lc;
        unsigned* vd = Vb + buf * 64 * VS + lrow * VS + lc;
#pragma unroll
        for (int j = 0; j < 4; j++) {
            cp_async16(kd + j * 4, kp + j * 4);
            cp_async16(vd + j * 4, vp + j * 4);
        }
        if (tid < 16)
            cp_async16(Mb + buf * 64 + tid * 4, mask + b * S + k0 + tid * 4);
    };

    float acc_o[8][4];
#pragma unroll
    for (int nt = 0; nt < 8; nt++)
#pragma unroll
        for (int j = 0; j < 4; j++) acc_o[nt][j] = 0.f;
    float m0r = -1e30f, m1r = -1e30f, l0 = 0.f, l1 = 0.f;

    unsigned fullm = 0xffffffffu;
    unsigned* Pw = Pb + warp * 16 * PS;

    issueKV(0, 0);
    CP_COMMIT;
    int cur = 0;

    for (int k0 = 0; k0 < S; k0 += 64) {
        CP_WAIT0;
        __syncthreads();
        if (k0 + 64 < S) {
            issueKV(cur ^ 1, k0 + 64);
            CP_COMMIT;
        }
        const unsigned* Kc = Kb + cur * 64 * KS;
        const unsigned* Vc = Vb + cur * 64 * VS;
        const int*      Mc = Mb + cur * 64;

        // ---- S = Q K^T (16x64) ----
        float sacc[8][4];
#pragma unroll
        for (int nt = 0; nt < 8; nt++)
#pragma unroll
            for (int j = 0; j < 4; j++) sacc[nt][j] = 0.f;
#pragma unroll
        for (int kk = 0; kk < 64; kk += 8) {
            int cc = kk >> 3;
#pragma unroll
            for (int nt = 0; nt < 8; nt++) {
                unsigned b0 = Kc[(nt * 8 + g) * KS + kk + cq    ];
                unsigned b1 = Kc[(nt * 8 + g) * KS + kk + cq + 4];
                MMA_TF32(sacc[nt][0], sacc[nt][1], sacc[nt][2], sacc[nt][3],
                         qf[cc][0], qf[cc][1], qf[cc][2], qf[cc][3], b0, b1);
            }
        }

        // ---- mask + online softmax ----
        float mx0 = -1e30f, mx1 = -1e30f;
#pragma unroll
        for (int nt = 0; nt < 8; nt++) {
            float mk0 = (Mc[nt * 8 + cq * 2]     == 0) ? -1e30f : 0.f;
            float mk1 = (Mc[nt * 8 + cq * 2 + 1] == 0) ? -1e30f : 0.f;
            sacc[nt][0] += mk0; sacc[nt][1] += mk1;
            sacc[nt][2] += mk0; sacc[nt][3] += mk1;
            mx0 = fmaxf(mx0, fmaxf(sacc[nt][0], sacc[nt][1]));
            mx1 = fmaxf(mx1, fmaxf(sacc[nt][2], sacc[nt][3]));
        }
        mx0 = fmaxf(mx0, __shfl_xor_sync(fullm, mx0, 1));
        mx0 = fmaxf(mx0, __shfl_xor_sync(fullm, mx0, 2));
        mx1 = fmaxf(mx1, __shfl_xor_sync(fullm, mx1, 1));
        mx1 = fmaxf(mx1, __shfl_xor_sync(fullm, mx1, 2));
        float newm0 = fmaxf(m0r, mx0), newm1 = fmaxf(m1r, mx1);
        float sc0 = __expf(m0r - newm0), sc1 = __expf(m1r - newm1);
        m0r = newm0; m1r = newm1;
        float ps0 = 0.f, ps1 = 0.f;
#pragma unroll
        for (int nt = 0; nt < 8; nt++) {
            sacc[nt][0] = __expf(sacc[nt][0] - newm0);
            sacc[nt][1] = __expf(sacc[nt][1] - newm0);
            sacc[nt][2] = __expf(sacc[nt][2] - newm1);
            sacc[nt][3] = __expf(sacc[nt][3] - newm1);
            ps0 += sacc[nt][0] + sacc[nt][1];
            ps1 += sacc[nt][2] + sacc[nt][3];
            acc_o[nt][0] *= sc0; acc_o[nt][1] *= sc0;
            acc_o[nt][2] *= sc1; acc_o[nt][3] *= sc1;
        }
        ps0 += __shfl_xor_sync(fullm, ps0, 1); ps0 += __shfl_xor_sync(fullm, ps0, 2);
        ps1 += __shfl_xor_sync(fullm, ps1, 1); ps1 += __shfl_xor_sync(fullm, ps1, 2);
        l0 = l0 * sc0 + ps0;
        l1 = l1 * sc1 + ps1;

        // ---- P -> smem (tf32), then PV via fragment loads ----
        __syncwarp();
#pragma unroll
        for (int nt = 0; nt < 8; nt++) {
            unsigned p0 = f2tf(sacc[nt][0]), p1 = f2tf(sacc[nt][1]);
            unsigned p2 = f2tf(sacc[nt][2]), p3 = f2tf(sacc[nt][3]);
            *(uint2*)(Pw + g * PS + nt * 8 + 2 * cq)       = make_uint2(p0, p1);
            *(uint2*)(Pw + (g + 8) * PS + nt * 8 + 2 * cq) = make_uint2(p2, p3);
        }
        __syncwarp();
#pragma unroll
        for (int kt = 0; kt < 8; kt++) {
            unsigned a0 = Pw[(g    ) * PS + kt * 8 + cq    ];
            unsigned a1 = Pw[(g + 8) * PS + kt * 8 + cq    ];
            unsigned a2 = Pw[(g    ) * PS + kt * 8 + cq + 4];
            unsigned a3 = Pw[(g + 8) * PS + kt * 8 + cq + 4];
#pragma unroll
            for (int nt = 0; nt < 8; nt++) {
                unsigned b0 = Vc[(kt * 8 + cq    ) * VS + nt * 8 + g];
                unsigned b1 = Vc[(kt * 8 + cq + 4) * VS + nt * 8 + g];
                MMA_TF32(acc_o[nt][0], acc_o[nt][1], acc_o[nt][2], acc_o[nt][3],
                         a0, a1, a2, a3, b0, b1);
            }
        }
        cur ^= 1;
    }

    // ---- epilogue: write tf32-rounded ctx (consumed as GEMM A) ----
    float inv0 = 1.f / l0, inv1 = 1.f / l1;
    size_t row0 = (size_t)(b * S + q0 + warp * 16 + g) * H + h * HD;
    size_t row1 = row0 + (size_t)8 * H;
#pragma unroll
    for (int nt = 0; nt < 8; nt++) {
        int col = nt * 8 + cq * 2;
        g_ctx[row0 + col]     = tfround(acc_o[nt][0] * inv0);
        g_ctx[row0 + col + 1] = tfround(acc_o[nt][1] * inv0);
        g_ctx[row1 + col]     = tfround(acc_o[nt][2] * inv1);
        g_ctx[row1 + col + 1] = tfround(acc_o[nt][3] * inv1);
    }
}

// ---------------- residual add + RMSNorm (+ optional tf32 copy) ------------
__global__ void addnorm_kernel(const float* __restrict__ a, const float* __restrict__ bb,
                               const float* __restrict__ w, float* __restrict__ out,
                               float* __restrict__ out_t) {
    __shared__ float buf[H];
    __shared__ float red[8];
    int t = blockIdx.x, tid = threadIdx.x;
    float ss = 0.f;
    for (int d = tid; d < H; d += 256) {
        float v = a[(size_t)t * H + d] + bb[(size_t)t * H + d];
        buf[d] = v;
        ss += v * v;
    }
    for (int o = 16; o; o >>= 1) ss += __shfl_xor_sync(~0u, ss, o);
    if ((tid & 31) == 0) red[tid >> 5] = ss;
    __syncthreads();
    if (tid < 8) {
        float x = red[tid];
        for (int o = 4; o; o >>= 1) x += __shfl_xor_sync(0xffu, x, o);
        if (tid == 0) red[0] = x;
    }
    __syncthreads();
    float inv = rsqrtf(red[0] / (float)H + 1.1920929e-7f);
    for (int d = tid; d < H; d += 256) {
        float v = buf[d] * inv * w[d];
        out[(size_t)t * H + d] = v;
        if (out_t) out_t[(size_t)t * H + d] = tfround(v);
    }
}

// ---------------- MoE combine (slots) + residual + RMSNorm -----------------
__global__ void moe_combine_norm(const float* __restrict__ w, float* __restrict__ out) {
    __shared__ float buf[H];
    __shared__ float red[8];
    int t = blockIdx.x, tid = threadIdx.x;
    int s0 = g_slot[t * 2], s1 = g_slot[t * 2 + 1];
    float w0 = g_slotw[t * 2], w1v = g_slotw[t * 2 + 1];
    float ss = 0.f;
    for (int d = tid; d < H; d += 256) {
        float v = g_x1[(size_t)t * H + d]
                + w0 * g_ybuf[(size_t)s0 * H + d]
                + w1v * g_ybuf[(size_t)s1 * H + d];
        buf[d] = v;
        ss += v * v;
    }
    for (int o = 16; o; o >>= 1) ss += __shfl_xor_sync(~0u, ss, o);
    if ((tid & 31) == 0) red[tid >> 5] = ss;
    __syncthreads();
    if (tid < 8) {
        float x = red[tid];
        for (int o = 4; o; o >>= 1) x += __shfl_xor_sync(0xffu, x, o);
        if (tid == 0) red[0] = x;
    }
    __syncthreads();
    float inv = rsqrtf(red[0] / (float)H + 1.1920929e-7f);
    for (int d = tid; d < H; d += 256)
        out[(size_t)t * H + d] = buf[d] * inv * w[d];
}

// ---------------- router -----------------------------------------------------
__global__ void router_kernel(const float* __restrict__ gate_w) {
    int warp = threadIdx.x >> 5, lane = threadIdx.x & 31;
    int t = blockIdx.x * 8 + warp;
    float acc[E];
#pragma unroll
    for (int e = 0; e < E; e++) acc[e] = 0.f;
    const float* xr = g_x1 + (size_t)t * H;
    for (int d = lane; d < H; d += 32) {
        float xv = xr[d];
        const float* g = gate_w + (size_t)d * E;
#pragma unroll
        for (int e = 0; e < E; e++) acc[e] += xv * g[e];
    }
#pragma unroll
    for (int e = 0; e < E; e++)
        for (int o = 16; o; o >>= 1) acc[e] += __shfl_xor_sync(~0u, acc[e], o);
    if (lane == 0) {
        float mx = acc[0];
#pragma unroll
        for (int e = 1; e < E; e++) mx = fmaxf(mx, acc[e]);
        float p[E]; float sum = 0.f;
#pragma unroll
        for (int e = 0; e < E; e++) { p[e] = expf(acc[e] - mx); sum += p[e]; }
        float inv = 1.f / sum;
#pragma unroll
        for (int e = 0; e < E; e++) p[e] *= inv;
        int i1 = 0;
#pragma unroll
        for (int e = 1; e < E; e++) if (p[e] > p[i1]) i1 = e;
        int i2 = -1;
#pragma unroll
        for (int e = 0; e < E; e++) {
            if (e == i1) continue;
            if (i2 < 0 || p[e] > p[i2]) i2 = e;
        }
        float s2 = p[i1] + p[i2];
        float w1n = p[i1] / s2, w2n = p[i2] / s2;
        int pos = atomicAdd(&g_cnt[i1], 1);
        g_tok[i1 * T + pos] = t;
        g_slot[t * 2] = i1 * T + pos;
        g_slotw[t * 2] = w1n;
        pos = atomicAdd(&g_cnt[i2], 1);
        g_tok[i2 * T + pos] = t;
        g_slot[t * 2 + 1] = i2 * T + pos;
        g_slotw[t * 2 + 1] = w2n;
#pragma unroll
        for (int e = 0; e < E; e++) atomicAdd(&g_probsum[e], p[e]);
    }
}

__global__ void aux_kernel(float* out) {
    float a = 0.f;
    for (int e = 0; e < E; e++)
        a += ((float)g_cnt[e] / (float)T) * (g_probsum[e] / (float)T);
    out[0] = (float)E * a;
}

// ---------------------------------------------------------------------------
extern "C" void kernel_launch(void* const* d_in, const int* in_sizes, int n_in,
                              void* d_out, int out_size) {
    const float* x      = (const float*)d_in[0];
    const int*   mask   = (const int*)  d_in[1];
    const float* qkv_w  = (const float*)d_in[2];
    const float* out_w  = (const float*)d_in[3];
    const float* gate_w = (const float*)d_in[4];
    const float* w1     = (const float*)d_in[5];
    const float* w2     = (const float*)d_in[6];
    const float* n1     = (const float*)d_in[7];
    const float* n2     = (const float*)d_in[8];
    float* out = (float*)d_out;

    float *p_qkv, *p_ctx, *p_attn, *p_x1, *p_x1t, *p_xt, *p_hmid;
    cudaGetSymbolAddress((void**)&p_qkv,  g_qkv);
    cudaGetSymbolAddress((void**)&p_ctx,  g_ctx);
    cudaGetSymbolAddress((void**)&p_attn, g_attn);
    cudaGetSymbolAddress((void**)&p_x1,   g_x1);
    cudaGetSymbolAddress((void**)&p_x1t,  g_x1t);
    cudaGetSymbolAddress((void**)&p_xt,   g_xt);
    cudaGetSymbolAddress((void**)&p_hmid, g_hmid);

    static bool attr_set = false;
    if (!attr_set) {
        cudaFuncSetAttribute(flash5_kernel,
                             cudaFuncAttributeMaxDynamicSharedMemorySize, FLASH_SMEM);
        cudaFuncSetAttribute(gemm_tf32<0>,
                             cudaFuncAttributeMaxDynamicSharedMemorySize, GEMM_SMEM);
        cudaFuncSetAttribute(gemm_tf32<1>,
                             cudaFuncAttributeMaxDynamicSharedMemorySize, GEMM_SMEM);
        cudaFuncSetAttribute(gemm_tf32<2>,
                             cudaFuncAttributeMaxDynamicSharedMemorySize, GEMM_SMEM);
        attr_set = true;
    }

    zero_small<<<1, 32>>>();

    // pre-round x for QKV GEMM A
    round_copy<<<(T * H + 255) / 256, 256>>>(x, p_xt, T * H);

    gemm_tf32<0><<<dim3(H3 / BN, T / BM, 1), 256, GEMM_SMEM>>>(p_xt, qkv_w, p_qkv, T, H3, H);

    rope2_kernel<<<(T * NH * 32 + 255) / 256, 256>>>();

    flash5_kernel<<<dim3(S / 128, NH, B), 256, FLASH_SMEM>>>(mask);

    gemm_tf32<0><<<dim3(H / BN, T / BM, 1), 256, GEMM_SMEM>>>(p_ctx, out_w, p_attn, T, H, H);

    addnorm_kernel<<<T, 256>>>(x, p_attn, n1, p_x1, p_x1t);

    router_kernel<<<T / 8, 256>>>(gate_w);
    aux_kernel<<<1, 1>>>(out + (size_t)T * H);

    gemm_tf32<1><<<dim3(F / BN, T / BM, E), 256, GEMM_SMEM>>>(p_x1t, w1, nullptr, T, F, H);
    gemm_tf32<2><<<dim3(H / BN, T / BM, E), 256, GEMM_SMEM>>>(p_hmid, w2, nullptr, T, H, F);

    moe_combine_norm<<<T, 256>>>(n2, out);
}